// round 9
// baseline (speedup 1.0000x reference)
#include <cuda_runtime.h>
#include <cuda_bf16.h>
#include <cstdint>

#define T_  4
#define B_  8192
#define D_  1024
#define U_  512
#define UE  4096

// ---------------------------------------------------------------------------
// Device scratch
// ---------------------------------------------------------------------------
__device__ float g_H[5ull * B_ * UE];
__device__ int8_t g_qx1[(size_t)B_ * D_];
__device__ int8_t g_qx2[(size_t)B_ * D_];
__device__ int8_t g_qb0a[5ull * UE * D_];     // level-0 B^T digit1 (N-major)
__device__ int8_t g_qb0b[5ull * UE * D_];     // digit2
__device__ int8_t g_qb1a[5ull * UE * U_];
__device__ int8_t g_qb1b[5ull * UE * U_];
__device__ int8_t g_qa1a[5ull * B_ * U_];     // level-1 A digits
__device__ int8_t g_qa1b[5ull * B_ * U_];
__device__ float g_g0[(size_t)T_ * B_ * 16];
__device__ float g_gs[(size_t)B_ * 40];
__device__ float g_task0[(size_t)T_ * B_ * U_];
__device__ float g_share[(size_t)B_ * U_];
__device__ float g_g1[(size_t)T_ * B_ * 16];
__device__ unsigned g_maxs[4];                // 0=x, 1=B0, 2=B1, 3=A1

// ---------------------------------------------------------------------------
// PTX helpers (baseline sm_80+ only)
// ---------------------------------------------------------------------------
__device__ __forceinline__ uint32_t smem_u32(const void* p) {
    uint32_t a;
    asm("{ .reg .u64 t; cvta.to.shared.u64 t, %1; cvt.u32.u64 %0, t; }" : "=r"(a) : "l"(p));
    return a;
}
__device__ __forceinline__ void cp16(uint32_t dst, const void* src) {
    asm volatile("cp.async.cg.shared.global [%0], [%1], 16;" :: "r"(dst), "l"(src));
}
__device__ __forceinline__ void ldsm4(uint32_t* r, uint32_t addr) {
    asm volatile("ldmatrix.sync.aligned.m8n8.x4.shared.b16 {%0,%1,%2,%3}, [%4];"
        : "=r"(r[0]), "=r"(r[1]), "=r"(r[2]), "=r"(r[3]) : "r"(addr));
}
__device__ __forceinline__ void imma(int* c, const uint32_t* a, uint32_t b0, uint32_t b1) {
    asm volatile("mma.sync.aligned.m16n8k32.row.col.s32.s8.s8.s32 "
        "{%0,%1,%2,%3}, {%4,%5,%6,%7}, {%8,%9}, {%0,%1,%2,%3};"
        : "+r"(c[0]), "+r"(c[1]), "+r"(c[2]), "+r"(c[3])
        : "r"(a[0]), "r"(a[1]), "r"(a[2]), "r"(a[3]), "r"(b0), "r"(b1));
}

// ---------------------------------------------------------------------------
// Scale discovery + quantization
// ---------------------------------------------------------------------------
__global__ void zeromax() { if (threadIdx.x < 4) g_maxs[threadIdx.x] = 0u; }

__global__ __launch_bounds__(256) void maxabs(const float* __restrict__ p, int slot) {
    const int i = blockIdx.x * 256 + threadIdx.x;
    float4 v = ((const float4*)p)[i];
    float m = fmaxf(fmaxf(fabsf(v.x), fabsf(v.y)), fmaxf(fabsf(v.z), fabsf(v.w)));
#pragma unroll
    for (int o = 16; o; o >>= 1) m = fmaxf(m, __shfl_xor_sync(0xffffffffu, m, o));
    __shared__ float sm[8];
    if ((threadIdx.x & 31) == 0) sm[threadIdx.x >> 5] = m;
    __syncthreads();
    if (threadIdx.x < 8) {
        m = sm[threadIdx.x];
#pragma unroll
        for (int o = 4; o; o >>= 1) m = fmaxf(m, __shfl_xor_sync(0xffu, m, o));
        if (threadIdx.x == 0) atomicMax(&g_maxs[slot], __float_as_uint(m));
    }
}

__device__ __forceinline__ void quant1(float v, float inv, int8_t& q1, int8_t& q2) {
    float q = v * inv;
    int a1 = __float2int_rn(q);
    float r = q - (float)a1;
    int a2 = __float2int_rn(r * 256.f);
    a2 = min(127, max(-128, a2));
    q1 = (int8_t)a1; q2 = (int8_t)a2;
}

__global__ __launch_bounds__(256) void quantRows(const float* __restrict__ src,
                                                 int8_t* __restrict__ q1,
                                                 int8_t* __restrict__ q2, int slot) {
    const size_t i = (size_t)blockIdx.x * 256 + threadIdx.x;
    const float inv = 127.f / __uint_as_float(g_maxs[slot]);
    float4 v = ((const float4*)src)[i];
    char4 c1, c2;
    quant1(v.x, inv, (int8_t&)c1.x, (int8_t&)c2.x);
    quant1(v.y, inv, (int8_t&)c1.y, (int8_t&)c2.y);
    quant1(v.z, inv, (int8_t&)c1.z, (int8_t&)c2.z);
    quant1(v.w, inv, (int8_t&)c1.w, (int8_t&)c2.w);
    ((char4*)q1)[i] = c1;
    ((char4*)q2)[i] = c2;
}

// A1 quant: 5 slots (4 tasks from g_task0, shared from g_share)
__global__ __launch_bounds__(256) void quantA1() {
    const int z = blockIdx.z;
    const size_t i = (size_t)blockIdx.x * 256 + threadIdx.x;
    const float inv = 127.f / __uint_as_float(g_maxs[3]);
    const float* src = (z < 4) ? (g_task0 + (size_t)z * B_ * U_) : g_share;
    float4 v = ((const float4*)src)[i];
    char4 c1, c2;
    quant1(v.x, inv, (int8_t&)c1.x, (int8_t&)c2.x);
    quant1(v.y, inv, (int8_t&)c1.y, (int8_t&)c2.y);
    quant1(v.z, inv, (int8_t&)c1.z, (int8_t&)c2.z);
    quant1(v.w, inv, (int8_t&)c1.w, (int8_t&)c2.w);
    ((char4*)(g_qa1a + (size_t)z * B_ * U_))[i] = c1;
    ((char4*)(g_qa1b + (size_t)z * B_ * U_))[i] = c2;
}

// B quant + transpose to N-major: src[k][n] fp32 -> q[slot][n][k] int8 digits
struct QBArgs { const float* src[5]; int8_t* q1; int8_t* q2; int K; int slot; };

__global__ void quantB(QBArgs a) {
    __shared__ float s[32][33];
    const int z = blockIdx.z;
    const float* __restrict__ src = a.src[z];
    const int n0 = blockIdx.x * 32, k0 = blockIdx.y * 32;
    const int tx = threadIdx.x, ty = threadIdx.y;   // (32, 8)
    const float inv = 127.f / __uint_as_float(g_maxs[a.slot]);
#pragma unroll
    for (int i = 0; i < 4; i++)
        s[ty + i * 8][tx] = src[(size_t)(k0 + ty + i * 8) * UE + n0 + tx];
    __syncthreads();
    int8_t* o1 = a.q1 + (size_t)z * UE * a.K;
    int8_t* o2 = a.q2 + (size_t)z * UE * a.K;
#pragma unroll
    for (int i = 0; i < 4; i++) {
        const int n = n0 + ty + i * 8, k = k0 + tx;
        int8_t q1v, q2v;
        quant1(s[tx][ty + i * 8], inv, q1v, q2v);
        o1[(size_t)n * a.K + k] = q1v;
        o2[(size_t)n * a.K + k] = q2v;
    }
}

// ---------------------------------------------------------------------------
// int8 GEMM: 128x128 tile, K-step 64 bytes, 4-stage cp.async, dual int32 acc.
// H[t] = relu( sA*sB*(acc1 + accX/256) + bias )
// ---------------------------------------------------------------------------
struct QGemmArgs {
    const int8_t *A1[5], *A2[5], *B1[5], *B2[5];
    const float* bias[5];
    float* H;
    int K;       // bytes per row
    int iA, iB;  // scale indices
};

#define KSTEP 64
#define MAT_BYTES 8192                     // 128 rows * 64B
#define STAGE_BYTES (4 * MAT_BYTES)        // 32 KB
#define NSTAGE 4
#define SMEM_BYTES (NSTAGE * STAGE_BYTES)  // 128 KB

__global__ __launch_bounds__(256, 1) void qgemm(QGemmArgs args) {
    extern __shared__ __align__(128) char smem[];
    const uint32_t sb = smem_u32(smem);

    // L2-aware rasterization: 16 consecutive CTAs share one (t, n0) B tile.
    const int id    = blockIdx.x;
    const int group = id / 2560;
    const int rem   = id - group * 2560;
    const int mt    = group * 16 + (rem & 15);
    const int ntid  = rem >> 4;
    const int t     = ntid >> 5;
    const int n0    = (ntid & 31) << 7;
    const int m0    = mt << 7;

    const int K  = args.K;
    const int nk = K / KSTEP;
    const int tid  = threadIdx.x;
    const int lane = tid & 31;
    const int w    = tid >> 5;
    const int wm   = w & 3;
    const int wn   = w >> 2;
    const int hb   = lane >> 4;

    const int8_t* __restrict__ srcs[4] = {
        args.A1[t] + (size_t)m0 * K, args.A2[t] + (size_t)m0 * K,
        args.B1[t] + (size_t)n0 * K, args.B2[t] + (size_t)n0 * K };

    const int rlo = tid >> 2;
    const int ch  = tid & 3;
    const int dsw = ((ch ^ ((rlo >> 1) & 3)) << 4);

    auto load_stage = [&](int buf, int kc) {
        const uint32_t base = sb + (uint32_t)buf * STAGE_BYTES;
#pragma unroll
        for (int i = 0; i < 8; i++) {
            const int mat = i >> 1;
            const int r   = ((i & 1) << 6) + rlo;
            cp16(base + mat * MAT_BYTES + r * 64 + dsw,
                 srcs[mat] + (size_t)r * K + kc + ch * 16);
        }
        asm volatile("cp.async.commit_group;" ::: "memory");
    };

    uint32_t aoff[2][2], boff[4][2];
#pragma unroll
    for (int i = 0; i < 2; i++) {
        const int rA = 32 * wm + 16 * i + (lane & 15);
        const int csw = (rA >> 1) & 3;
#pragma unroll
        for (int ks = 0; ks < 2; ks++)
            aoff[i][ks] = (uint32_t)(rA * 64 + (((2 * ks + hb) ^ csw) << 4));
    }
#pragma unroll
    for (int j = 0; j < 4; j++) {
        const int rB = 64 * wn + 16 * j + (((lane >> 3) & 1) << 3) + (lane & 7);
        const int csw = (rB >> 1) & 3;
#pragma unroll
        for (int ks = 0; ks < 2; ks++)
            boff[j][ks] = (uint32_t)(rB * 64 + (((2 * ks + hb) ^ csw) << 4));
    }

    int acc1[2][8][4], accX[2][8][4];
#pragma unroll
    for (int i = 0; i < 2; i++)
#pragma unroll
        for (int j = 0; j < 8; j++)
#pragma unroll
            for (int q = 0; q < 4; q++) { acc1[i][j][q] = 0; accX[i][j][q] = 0; }

    load_stage(0, 0);
    load_stage(1, KSTEP);
    load_stage(2, 2 * KSTEP);

    for (int c = 0; c < nk; c++) {
        const int remk = nk - c;
        if (remk >= 3)      asm volatile("cp.async.wait_group 2;" ::: "memory");
        else if (remk == 2) asm volatile("cp.async.wait_group 1;" ::: "memory");
        else                asm volatile("cp.async.wait_group 0;" ::: "memory");
        __syncthreads();
        if (c + 3 < nk) load_stage((c + 3) & 3, (c + 3) * KSTEP);

        const uint32_t st = sb + (uint32_t)(c & 3) * STAGE_BYTES;

#pragma unroll
        for (int ks = 0; ks < 2; ks++) {
            uint32_t a1f[2][4], a2f[2][4];
#pragma unroll
            for (int i = 0; i < 2; i++) {
                ldsm4(a1f[i], st + aoff[i][ks]);
                ldsm4(a2f[i], st + MAT_BYTES + aoff[i][ks]);
            }
            uint32_t bf[4][4];
#pragma unroll
            for (int j = 0; j < 4; j++) ldsm4(bf[j], st + 2 * MAT_BYTES + boff[j][ks]);
#pragma unroll
            for (int i = 0; i < 2; i++)
#pragma unroll
                for (int j = 0; j < 4; j++) {
                    imma(acc1[i][2 * j],     a1f[i], bf[j][0], bf[j][2]);
                    imma(acc1[i][2 * j + 1], a1f[i], bf[j][1], bf[j][3]);
                    imma(accX[i][2 * j],     a2f[i], bf[j][0], bf[j][2]);
                    imma(accX[i][2 * j + 1], a2f[i], bf[j][1], bf[j][3]);
                }
#pragma unroll
            for (int j = 0; j < 4; j++) ldsm4(bf[j], st + 3 * MAT_BYTES + boff[j][ks]);
#pragma unroll
            for (int i = 0; i < 2; i++)
#pragma unroll
                for (int j = 0; j < 4; j++) {
                    imma(accX[i][2 * j],     a1f[i], bf[j][0], bf[j][2]);
                    imma(accX[i][2 * j + 1], a1f[i], bf[j][1], bf[j][3]);
                }
        }
    }

    // epilogue: dequant + bias + relu
    const float sA = __uint_as_float(g_maxs[args.iA]) * (1.f / 127.f);
    const float sB = __uint_as_float(g_maxs[args.iB]) * (1.f / 127.f);
    const float s1 = sA * sB;
    const float sx = s1 * (1.f / 256.f);
    const float* __restrict__ bias = args.bias[t];
    float* __restrict__ Hb = args.H + (size_t)t * B_ * UE;
#pragma unroll
    for (int i = 0; i < 2; i++) {
        const int mr = m0 + 32 * wm + 16 * i + (lane >> 2);
#pragma unroll
        for (int j = 0; j < 8; j++) {
            const int nc = n0 + 64 * wn + 8 * j + ((lane & 3) << 1);
            const float b0v = bias[nc], b1v = bias[nc + 1];
            float2 o0, o1;
            o0.x = fmaxf(fmaf((float)accX[i][j][0], sx, (float)acc1[i][j][0] * s1) + b0v, 0.f);
            o0.y = fmaxf(fmaf((float)accX[i][j][1], sx, (float)acc1[i][j][1] * s1) + b1v, 0.f);
            o1.x = fmaxf(fmaf((float)accX[i][j][2], sx, (float)acc1[i][j][2] * s1) + b0v, 0.f);
            o1.y = fmaxf(fmaf((float)accX[i][j][3], sx, (float)acc1[i][j][3] * s1) + b1v, 0.f);
            *(float2*)(Hb + (size_t)mr * UE + nc)       = o0;
            *(float2*)(Hb + (size_t)(mr + 8) * UE + nc) = o1;
        }
    }
}

// ---------------------------------------------------------------------------
// gates0 / gates1 (R8 fast versions, unchanged)
// ---------------------------------------------------------------------------
__global__ __launch_bounds__(256) void gates0(const float* __restrict__ x,
                                              const float* __restrict__ gw0,
                                              const float* __restrict__ gb0,
                                              const float* __restrict__ gws,
                                              const float* __restrict__ gbs) {
    const int b0 = blockIdx.x * 16;
    const int tid = threadIdx.x;
    __shared__ float sx[16][128];
    __shared__ float sz[16][104];

    const bool active = tid < 208;
    const int rh = (tid >= 104) ? 1 : 0;
    const int c  = active ? (tid - rh * 104) : 0;

    const float* Wp; int wstride;
    if (c < 64) { Wp = gw0 + (size_t)(c >> 4) * D_ * 16 + (c & 15); wstride = 16; }
    else        { Wp = gws + (c - 64);                              wstride = 40; }

    float acc[8];
#pragma unroll
    for (int r = 0; r < 8; r++) acc[r] = 0.f;

    for (int kc = 0; kc < D_ / 128; kc++) {
        __syncthreads();
#pragma unroll
        for (int p = 0; p < 2; p++) {
            const int idx = tid + p * 256;
            const int row = idx >> 5, c4 = idx & 31;
            *(float4*)&sx[row][c4 * 4] =
                *(const float4*)(x + (size_t)(b0 + row) * D_ + kc * 128 + c4 * 4);
        }
        __syncthreads();
        if (active) {
            const float* wp = Wp + (size_t)kc * 128 * wstride;
#pragma unroll 4
            for (int k = 0; k < 128; k += 4) {
                const float w0 = wp[(k + 0) * wstride];
                const float w1 = wp[(k + 1) * wstride];
                const float w2 = wp[(k + 2) * wstride];
                const float w3 = wp[(k + 3) * wstride];
#pragma unroll
                for (int r = 0; r < 8; r++) {
                    float4 xv = *(const float4*)&sx[rh * 8 + r][k];
                    acc[r] += xv.x * w0 + xv.y * w1 + xv.z * w2 + xv.w * w3;
                }
            }
        }
    }
    if (active) {
        const float bb = (c < 64) ? gb0[c] : gbs[c - 64];
#pragma unroll
        for (int r = 0; r < 8; r++) sz[rh * 8 + r][c] = acc[r] + bb;
    }
    __syncthreads();

    if (tid < 80) {
        const int r = tid & 15, g = tid >> 4;
        const int base = (g < 4) ? g * 16 : 64;
        const int len  = (g < 4) ? 16 : 40;
        float mx = -1e30f;
        for (int i = 0; i < len; i++) mx = fmaxf(mx, sz[r][base + i]);
        float s = 0.f;
        for (int i = 0; i < len; i++) s += expf(sz[r][base + i] - mx);
        const float inv = 1.f / s;
        if (g < 4) {
            float* o = g_g0 + ((size_t)g * B_ + b0 + r) * 16;
            for (int i = 0; i < 16; i++) o[i] = expf(sz[r][base + i] - mx) * inv;
        } else {
            float* o = g_gs + (size_t)(b0 + r) * 40;
            for (int i = 0; i < 40; i++) o[i] = expf(sz[r][base + i] - mx) * inv;
        }
    }
}

__global__ __launch_bounds__(256) void gates1(const float* __restrict__ gw1,
                                              const float* __restrict__ gb1) {
    const int b0 = blockIdx.x * 16;
    const int tid = threadIdx.x;
    __shared__ float s1[4][16][128];
    __shared__ float sz[16][64];

    const bool active = tid < 128;
    const int rh = (tid >> 6) & 1;
    const int c  = tid & 63;
    const int tt = c >> 4;
    const float* Wp = gw1 + (size_t)tt * U_ * 16 + (c & 15);

    float acc[8];
#pragma unroll
    for (int r = 0; r < 8; r++) acc[r] = 0.f;

    for (int kc = 0; kc < U_ / 128; kc++) {
        __syncthreads();
#pragma unroll
        for (int p = 0; p < 8; p++) {
            const int idx = tid + p * 256;
            const int tz = idx >> 9, row = (idx >> 5) & 15, c4 = idx & 31;
            *(float4*)&s1[tz][row][c4 * 4] =
                *(const float4*)(g_task0 + ((size_t)tz * B_ + b0 + row) * U_ + kc * 128 + c4 * 4);
        }
        __syncthreads();
        if (active) {
            const float* wp = Wp + (size_t)kc * 128 * 16;
#pragma unroll 4
            for (int k = 0; k < 128; k += 4) {
                const float w0 = wp[(k + 0) * 16];
                const float w1 = wp[(k + 1) * 16];
                const float w2 = wp[(k + 2) * 16];
                const float w3 = wp[(k + 3) * 16];
#pragma unroll
                for (int r = 0; r < 8; r++) {
                    float4 xv = *(const float4*)&s1[tt][rh * 8 + r][k];
                    acc[r] += xv.x * w0 + xv.y * w1 + xv.z * w2 + xv.w * w3;
                }
            }
        }
    }
    if (active) {
        const float bb = gb1[c];
#pragma unroll
        for (int r = 0; r < 8; r++) sz[rh * 8 + r][c] = acc[r] + bb;
    }
    __syncthreads();

    if (tid < 64) {
        const int r = tid & 15, g = tid >> 4;
        float mx = -1e30f;
        for (int i = 0; i < 16; i++) mx = fmaxf(mx, sz[r][g * 16 + i]);
        float s = 0.f;
        for (int i = 0; i < 16; i++) s += expf(sz[r][g * 16 + i] - mx);
        const float inv = 1.f / s;
        float* o = g_g1 + ((size_t)g * B_ + b0 + r) * 16;
        for (int i = 0; i < 16; i++) o[i] = expf(sz[r][g * 16 + i] - mx) * inv;
    }
}

// ---------------------------------------------------------------------------
// Combines
// ---------------------------------------------------------------------------
__global__ __launch_bounds__(512) void combine0() {
    const int b = blockIdx.x;
    const int u = threadIdx.x;
    __shared__ float sg0[4][16];
    __shared__ float sgs[40];
    __shared__ float smax[16];
    if (threadIdx.x < 64) {
        const int t = threadIdx.x >> 4, j = threadIdx.x & 15;
        sg0[t][j] = g_g0[((size_t)t * B_ + b) * 16 + j];
    } else if (threadIdx.x < 104) {
        sgs[threadIdx.x - 64] = g_gs[(size_t)b * 40 + (threadIdx.x - 64)];
    }
    __syncthreads();

    float h[5][8];
#pragma unroll
    for (int t = 0; t < 5; t++) {
        const float* p = g_H + ((size_t)t * B_ + b) * UE + (u << 3);
        *(float4*)(h[t]) = *(const float4*)(p);
        *(float4*)(h[t] + 4) = *(const float4*)(p + 4);
    }

    float sh = 0.f, lm = 0.f;
#pragma unroll
    for (int t = 0; t < 4; t++) {
        float to = 0.f;
#pragma unroll
        for (int e = 0; e < 8; e++) {
            to += h[t][e] * sg0[t][e] + h[4][e] * sg0[t][8 + e];
            sh += h[t][e] * sgs[t * 8 + e];
        }
        g_task0[((size_t)t * B_ + b) * U_ + u] = to;
        lm = fmaxf(lm, fabsf(to));
    }
#pragma unroll
    for (int e = 0; e < 8; e++) sh += h[4][e] * sgs[32 + e];
    g_share[(size_t)b * U_ + u] = sh;
    lm = fmaxf(lm, fabsf(sh));

    // block max -> atomicMax(g_maxs[3])
#pragma unroll
    for (int o = 16; o; o >>= 1) lm = fmaxf(lm, __shfl_xor_sync(0xffffffffu, lm, o));
    if ((threadIdx.x & 31) == 0) smax[threadIdx.x >> 5] = lm;
    __syncthreads();
    if (threadIdx.x < 16) {
        lm = smax[threadIdx.x];
#pragma unroll
        for (int o = 8; o; o >>= 1) lm = fmaxf(lm, __shfl_xor_sync(0xffffu, lm, o));
        if (threadIdx.x == 0) atomicMax(&g_maxs[3], __float_as_uint(lm));
    }
}

__global__ __launch_bounds__(512) void combine1(float* __restrict__ out) {
    const int b = blockIdx.x;
    const int u = threadIdx.x;
    __shared__ float sg[4][16];
    if (threadIdx.x < 64) {
        const int t = threadIdx.x >> 4, j = threadIdx.x & 15;
        sg[t][j] = g_g1[((size_t)t * B_ + b) * 16 + j];
    }
    __syncthreads();
    float h[5][8];
#pragma unroll
    for (int t = 0; t < 5; t++) {
        const float* p = g_H + ((size_t)t * B_ + b) * UE + (u << 3);
        *(float4*)(h[t]) = *(const float4*)(p);
        *(float4*)(h[t] + 4) = *(const float4*)(p + 4);
    }
#pragma unroll
    for (int t = 0; t < 4; t++) {
        float o = 0.f;
#pragma unroll
        for (int e = 0; e < 8; e++)
            o += h[t][e] * sg[t][e] + h[4][e] * sg[t][8 + e];
        out[((size_t)t * B_ + b) * U_ + u] = o;
    }
}

// ---------------------------------------------------------------------------
// Launch
// ---------------------------------------------------------------------------
extern "C" void kernel_launch(void* const* d_in, const int* in_sizes, int n_in,
                              void* d_out, int out_size) {
    (void)in_sizes; (void)n_in; (void)out_size;
    const float* x    = (const float*)d_in[0];
    const float* ews0 = (const float*)d_in[1];
    const float* ebs0 = (const float*)d_in[2];
    const float* ews1 = (const float*)d_in[3];
    const float* ebs1 = (const float*)d_in[4];
    const float* gws  = (const float*)d_in[5];
    const float* gbs  = (const float*)d_in[6];
    const float* ew0  = (const float*)d_in[7];
    const float* eb0  = (const float*)d_in[8];
    const float* gw0  = (const float*)d_in[9];
    const float* gb0  = (const float*)d_in[10];
    const float* ew1  = (const float*)d_in[11];
    const float* eb1  = (const float*)d_in[12];
    const float* gw1  = (const float*)d_in[13];
    const float* gb1  = (const float*)d_in[14];

    cudaFuncSetAttribute(qgemm, cudaFuncAttributeMaxDynamicSharedMemorySize, SMEM_BYTES);

    float* H; cudaGetSymbolAddress((void**)&H, g_H);
    int8_t *qx1, *qx2, *qb0a, *qb0b, *qb1a, *qb1b, *qa1a, *qa1b;
    cudaGetSymbolAddress((void**)&qx1,  g_qx1);
    cudaGetSymbolAddress((void**)&qx2,  g_qx2);
    cudaGetSymbolAddress((void**)&qb0a, g_qb0a);
    cudaGetSymbolAddress((void**)&qb0b, g_qb0b);
    cudaGetSymbolAddress((void**)&qb1a, g_qb1a);
    cudaGetSymbolAddress((void**)&qb1b, g_qb1b);
    cudaGetSymbolAddress((void**)&qa1a, g_qa1a);
    cudaGetSymbolAddress((void**)&qa1b, g_qa1b);

    // ---- scales ----
    zeromax<<<1, 32>>>();
    maxabs<<<(B_ * D_) / 1024, 256>>>(x, 0);
    maxabs<<<(4 * D_ * UE) / 1024, 256>>>(ew0, 1);
    maxabs<<<(D_ * UE) / 1024, 256>>>(ews0, 1);
    maxabs<<<(4 * U_ * UE) / 1024, 256>>>(ew1, 2);
    maxabs<<<(U_ * UE) / 1024, 256>>>(ews1, 2);

    // ---- quantize inputs & weights ----
    quantRows<<<(B_ * D_) / 1024, 256>>>(x, qx1, qx2, 0);
    QBArgs qb0;
    for (int t = 0; t < 4; t++) qb0.src[t] = ew0 + (size_t)t * D_ * UE;
    qb0.src[4] = ews0; qb0.q1 = qb0a; qb0.q2 = qb0b; qb0.K = D_; qb0.slot = 1;
    quantB<<<dim3(UE / 32, D_ / 32, 5), dim3(32, 8)>>>(qb0);
    QBArgs qb1;
    for (int t = 0; t < 4; t++) qb1.src[t] = ew1 + (size_t)t * U_ * UE;
    qb1.src[4] = ews1; qb1.q1 = qb1a; qb1.q2 = qb1b; qb1.K = U_; qb1.slot = 2;
    quantB<<<dim3(UE / 32, U_ / 32, 5), dim3(32, 8)>>>(qb1);

    // ---- level 0 ----
    gates0<<<B_ / 16, 256>>>(x, gw0, gb0, gws, gbs);
    QGemmArgs a0;
    for (int t = 0; t < 5; t++) { a0.A1[t] = qx1; a0.A2[t] = qx2; }
    for (int t = 0; t < 5; t++) {
        a0.B1[t] = qb0a + (size_t)t * UE * D_;
        a0.B2[t] = qb0b + (size_t)t * UE * D_;
    }
    for (int t = 0; t < 4; t++) a0.bias[t] = eb0 + (size_t)t * UE;
    a0.bias[4] = ebs0;
    a0.H = H; a0.K = D_; a0.iA = 0; a0.iB = 1;
    qgemm<<<10240, 256, SMEM_BYTES>>>(a0);
    combine0<<<B_, 512>>>();

    // ---- level 1 ----
    quantA1<<<dim3((B_ * U_) / 1024, 1, 5), 256>>>();
    gates1<<<B_ / 16, 256>>>(gw1, gb1);
    QGemmArgs a1;
    for (int t = 0; t < 5; t++) {
        a1.A1[t] = qa1a + (size_t)t * B_ * U_;
        a1.A2[t] = qa1b + (size_t)t * B_ * U_;
        a1.B1[t] = qb1a + (size_t)t * UE * U_;
        a1.B2[t] = qb1b + (size_t)t * UE * U_;
    }
    for (int t = 0; t < 4; t++) a1.bias[t] = eb1 + (size_t)t * UE;
    a1.bias[4] = ebs1;
    a1.H = H; a1.K = U_; a1.iA = 3; a1.iB = 2;
    qgemm<<<10240, 256, SMEM_BYTES>>>(a1);
    combine1<<<B_, 512>>>((float*)d_out);
}

// round 10
// speedup vs baseline: 2.2139x; 2.2139x over previous
#include <cuda_runtime.h>
#include <cuda_bf16.h>
#include <cstdint>

#define T_  4
#define B_  8192
#define D_  1024
#define U_  512
#define UE  4096
#define NTOT 4096

// ---------------------------------------------------------------------------
// Device scratch
// ---------------------------------------------------------------------------
__device__ __nv_bfloat16 g_xhi[(size_t)B_ * D_];
__device__ __nv_bfloat16 g_xlo[(size_t)B_ * D_];
__device__ __nv_bfloat16 g_bt0h[5ull * NTOT * D_];   // level-0 B^T hi (N-major)
__device__ __nv_bfloat16 g_bt0l[5ull * NTOT * D_];
__device__ __nv_bfloat16 g_bt1h[5ull * NTOT * U_];
__device__ __nv_bfloat16 g_bt1l[5ull * NTOT * U_];
__device__ __nv_bfloat16 g_a1h[5ull * B_ * U_];      // level-1 A (4 tasks + share)
__device__ __nv_bfloat16 g_a1l[5ull * B_ * U_];
__device__ float g_g0[(size_t)T_ * B_ * 16];
__device__ float g_gs[(size_t)B_ * 40];
__device__ float g_task0[(size_t)T_ * B_ * U_];      // fp32 (gates1 input)
__device__ float g_g1[(size_t)T_ * B_ * 16];

// ---------------------------------------------------------------------------
// PTX helpers (baseline sm_80+ only)
// ---------------------------------------------------------------------------
__device__ __forceinline__ uint32_t smem_u32(const void* p) {
    uint32_t a;
    asm("{ .reg .u64 t; cvta.to.shared.u64 t, %1; cvt.u32.u64 %0, t; }" : "=r"(a) : "l"(p));
    return a;
}
__device__ __forceinline__ void cp16(uint32_t dst, const void* src) {
    asm volatile("cp.async.cg.shared.global [%0], [%1], 16;" :: "r"(dst), "l"(src));
}
__device__ __forceinline__ void ldsm4(uint32_t* r, uint32_t addr) {
    asm volatile("ldmatrix.sync.aligned.m8n8.x4.shared.b16 {%0,%1,%2,%3}, [%4];"
        : "=r"(r[0]), "=r"(r[1]), "=r"(r[2]), "=r"(r[3]) : "r"(addr));
}
__device__ __forceinline__ void mma16816(float* c, const uint32_t* a, uint32_t b0, uint32_t b1) {
    asm volatile("mma.sync.aligned.m16n8k16.row.col.f32.bf16.bf16.f32 "
        "{%0,%1,%2,%3}, {%4,%5,%6,%7}, {%8,%9}, {%0,%1,%2,%3};"
        : "+f"(c[0]), "+f"(c[1]), "+f"(c[2]), "+f"(c[3])
        : "r"(a[0]), "r"(a[1]), "r"(a[2]), "r"(a[3]), "r"(b0), "r"(b1));
}
__device__ __forceinline__ float red4(float p) {
    p += __shfl_xor_sync(0xffffffffu, p, 1);
    p += __shfl_xor_sync(0xffffffffu, p, 2);
    return p;
}
__device__ __forceinline__ void store_a1(__nv_bfloat16* h, __nv_bfloat16* l,
                                         size_t off, float4 v) {
    __nv_bfloat16 h0 = __float2bfloat16(v.x), h1 = __float2bfloat16(v.y);
    __nv_bfloat16 h2 = __float2bfloat16(v.z), h3 = __float2bfloat16(v.w);
    *(__nv_bfloat162*)&h[off]     = __nv_bfloat162(h0, h1);
    *(__nv_bfloat162*)&h[off + 2] = __nv_bfloat162(h2, h3);
    *(__nv_bfloat162*)&l[off] = __nv_bfloat162(
        __float2bfloat16(v.x - __bfloat162float(h0)),
        __float2bfloat16(v.y - __bfloat162float(h1)));
    *(__nv_bfloat162*)&l[off + 2] = __nv_bfloat162(
        __float2bfloat16(v.z - __bfloat162float(h2)),
        __float2bfloat16(v.w - __bfloat162float(h3)));
}

// ---------------------------------------------------------------------------
// Conversions (fp32 -> bf16 hi/lo; B transposed to N-major)
// ---------------------------------------------------------------------------
__global__ void convX(const float* __restrict__ x, __nv_bfloat16* __restrict__ hi,
                      __nv_bfloat16* __restrict__ lo) {
    size_t i = (size_t)blockIdx.x * blockDim.x + threadIdx.x;
    float4 v = ((const float4*)x)[i];
    store_a1(hi, lo, 4 * i, v);
}

struct ConvBArgs { const float* src[5]; __nv_bfloat16* hi; __nv_bfloat16* lo; int K; };

__global__ void convB(ConvBArgs a) {
    __shared__ float s[32][33];
    const int z = blockIdx.z;
    const float* __restrict__ src = a.src[z];
    const int n0 = blockIdx.x * 32, k0 = blockIdx.y * 32;
    const int tx = threadIdx.x, ty = threadIdx.y;
#pragma unroll
    for (int i = 0; i < 4; i++)
        s[ty + i * 8][tx] = src[(size_t)(k0 + ty + i * 8) * UE + n0 + tx];
    __syncthreads();
    __nv_bfloat16* oh = a.hi + (size_t)z * NTOT * a.K;
    __nv_bfloat16* ol = a.lo + (size_t)z * NTOT * a.K;
#pragma unroll
    for (int i = 0; i < 4; i++) {
        const int n = n0 + ty + i * 8, k = k0 + tx;
        float v = s[tx][ty + i * 8];
        __nv_bfloat16 h = __float2bfloat16(v);
        oh[(size_t)n * a.K + k] = h;
        ol[(size_t)n * a.K + k] = __float2bfloat16(v - __bfloat162float(h));
    }
}

// ---------------------------------------------------------------------------
// Fused GEMM machinery: 128x128 tile, K-step 32, 4-stage cp.async,
// 8 warps (32x64 each), bf16 3-term split.
// ---------------------------------------------------------------------------
#define MAT_BYTES 8192
#define STAGE_BYTES (4 * MAT_BYTES)       // 32 KB

// smem layout (bytes)
#define SM_SG    131072                   // gates: float[128][68]
#define SM_SGS   165888                   // gs:    float[128][40]  (level-0 only)
#define SM_SSH0  186368                   // share accum: float[128][16]
#define SM_STK0  194560                   // staging: float[128][16]
#define SMEM0    202752
#define SM_STK1  165888
#define SMEM1    174080

template<int KK>
__device__ __forceinline__ void kloop(const __nv_bfloat16* __restrict__ A_h,
                                      const __nv_bfloat16* __restrict__ A_l,
                                      const __nv_bfloat16* __restrict__ B_h,
                                      const __nv_bfloat16* __restrict__ B_l,
                                      uint32_t sb, int rlo, int ch, int dsw,
                                      const uint32_t (&aoff)[2][2],
                                      const uint32_t (&boff)[4][2],
                                      float (&acc)[2][8][4]) {
    constexpr int nk = KK / 32;
    const __nv_bfloat16* srcs[4] = { A_h, A_l, B_h, B_l };
    auto load_stage = [&](int buf, int kc) {
        const uint32_t base = sb + (uint32_t)buf * STAGE_BYTES;
#pragma unroll
        for (int i = 0; i < 8; i++) {
            const int mat = i >> 1;
            const int r   = ((i & 1) << 6) + rlo;
            cp16(base + mat * MAT_BYTES + r * 64 + dsw,
                 srcs[mat] + (size_t)r * KK + kc + ch * 8);
        }
        asm volatile("cp.async.commit_group;" ::: "memory");
    };
    load_stage(0, 0); load_stage(1, 32); load_stage(2, 64);
    for (int c = 0; c < nk; c++) {
        const int rem = nk - c;
        if (rem >= 3)      asm volatile("cp.async.wait_group 2;" ::: "memory");
        else if (rem == 2) asm volatile("cp.async.wait_group 1;" ::: "memory");
        else               asm volatile("cp.async.wait_group 0;" ::: "memory");
        __syncthreads();
        if (c + 3 < nk) load_stage((c + 3) & 3, (c + 3) * 32);
        const uint32_t st = sb + (uint32_t)(c & 3) * STAGE_BYTES;
#pragma unroll
        for (int ks = 0; ks < 2; ks++) {
            uint32_t ahi[2][4], alo[2][4];
#pragma unroll
            for (int i = 0; i < 2; i++) {
                ldsm4(ahi[i], st + aoff[i][ks]);
                ldsm4(alo[i], st + MAT_BYTES + aoff[i][ks]);
            }
            uint32_t bf[4][4];
#pragma unroll
            for (int j = 0; j < 4; j++) ldsm4(bf[j], st + 2 * MAT_BYTES + boff[j][ks]);
#pragma unroll
            for (int i = 0; i < 2; i++)
#pragma unroll
                for (int j = 0; j < 4; j++) {
                    mma16816(acc[i][2 * j],     ahi[i], bf[j][0], bf[j][2]);
                    mma16816(acc[i][2 * j + 1], ahi[i], bf[j][1], bf[j][3]);
                    mma16816(acc[i][2 * j],     alo[i], bf[j][0], bf[j][2]);
                    mma16816(acc[i][2 * j + 1], alo[i], bf[j][1], bf[j][3]);
                }
#pragma unroll
            for (int j = 0; j < 4; j++) ldsm4(bf[j], st + 3 * MAT_BYTES + boff[j][ks]);
#pragma unroll
            for (int i = 0; i < 2; i++)
#pragma unroll
                for (int j = 0; j < 4; j++) {
                    mma16816(acc[i][2 * j],     ahi[i], bf[j][0], bf[j][2]);
                    mma16816(acc[i][2 * j + 1], ahi[i], bf[j][1], bf[j][3]);
                }
        }
    }
}

// macro: common per-CTA geometry
#define GEOM() \
    const int id = blockIdx.x; \
    const int nt = (id >> 4) & 31; \
    const int mt = (id & 15) + ((id >> 9) << 4); \
    const int n0 = nt << 7, m0 = mt << 7; \
    const int u0 = nt << 4; \
    const int tid = threadIdx.x; \
    const int lane = tid & 31; \
    const int w = tid >> 5, wm = w & 3, wn = w >> 2, hb = lane >> 4; \
    const int rlo = tid >> 2, ch = tid & 3; \
    const int dsw = ((ch ^ ((rlo >> 1) & 3)) << 4); \
    uint32_t aoff[2][2], boff[4][2]; \
    _Pragma("unroll") for (int i = 0; i < 2; i++) { \
        const int rA = 32 * wm + 16 * i + (lane & 15); \
        const int csw = (rA >> 1) & 3; \
        _Pragma("unroll") for (int ks = 0; ks < 2; ks++) \
            aoff[i][ks] = (uint32_t)(rA * 64 + (((2 * ks + hb) ^ csw) << 4)); \
    } \
    _Pragma("unroll") for (int j = 0; j < 4; j++) { \
        const int rB = 64 * wn + 16 * j + (((lane >> 3) & 1) << 3) + (lane & 7); \
        const int csw = (rB >> 1) & 3; \
        _Pragma("unroll") for (int ks = 0; ks < 2; ks++) \
            boff[j][ks] = (uint32_t)(rB * 64 + (((2 * ks + hb) ^ csw) << 4)); \
    }

struct FGArgs {
    const __nv_bfloat16 *Bh[5], *Bl[5];
    const float* bias[5];
};

// ---------------------------------------------------------------------------
// Level-0 fused GEMM: experts + gate combine; writes task0 (fp32) and a1 bf16.
// ---------------------------------------------------------------------------
__global__ __launch_bounds__(256, 1) void fgemm0(FGArgs args) {
    extern __shared__ __align__(128) char smem[];
    const uint32_t sb = smem_u32(smem);
    float* sg  = (float*)(smem + SM_SG);    // [128][68]
    float* sgs = (float*)(smem + SM_SGS);   // [128][40]
    float* ssh = (float*)(smem + SM_SSH0);  // [128][16]
    float* stk = (float*)(smem + SM_STK0);  // [128][16]
    GEOM();

    // load gates
    for (int idx = tid; idx < 2048; idx += 256) {
        const int r = idx >> 4, c4 = idx & 15;
        const int tt = c4 >> 2, o = (c4 & 3) << 2;
        *(float4*)&sg[r * 68 + tt * 16 + o] =
            *(const float4*)&g_g0[((size_t)tt * B_ + m0 + r) * 16 + o];
    }
    for (int idx = tid; idx < 1280; idx += 256) {
        const int r = idx / 10, c4 = idx % 10;
        *(float4*)&sgs[r * 40 + c4 * 4] =
            *(const float4*)&g_gs[(size_t)(m0 + r) * 40 + c4 * 4];
    }
    for (int idx = tid; idx < 2048; idx += 256) ssh[idx] = 0.f;
    __syncthreads();

    const __nv_bfloat16* Ah = g_xhi + (size_t)m0 * D_;
    const __nv_bfloat16* Al = g_xlo + (size_t)m0 * D_;
    float esr[2][8][4];
    const int e2 = 2 * (lane & 3);

    const int order[5] = {4, 0, 1, 2, 3};
#pragma unroll 1
    for (int ti = 0; ti < 5; ti++) {
        const int t = order[ti];
        float acc[2][8][4];
#pragma unroll
        for (int i = 0; i < 2; i++)
#pragma unroll
            for (int j = 0; j < 8; j++)
#pragma unroll
                for (int q = 0; q < 4; q++) acc[i][j][q] = 0.f;

        kloop<D_>(Ah, Al, args.Bh[t] + (size_t)n0 * D_, args.Bl[t] + (size_t)n0 * D_,
                  sb, rlo, ch, dsw, aoff, boff, acc);

        const float* __restrict__ bias = args.bias[t];
        if (t == 4) {
#pragma unroll
            for (int i = 0; i < 2; i++) {
                const int r0 = 32 * wm + 16 * i + (lane >> 2), r1 = r0 + 8;
#pragma unroll
                for (int j = 0; j < 8; j++) {
                    const int ncl = 64 * wn + 8 * j + e2;
                    const float b0v = bias[n0 + ncl], b1v = bias[n0 + ncl + 1];
                    float v00 = fmaxf(acc[i][j][0] + b0v, 0.f);
                    float v01 = fmaxf(acc[i][j][1] + b1v, 0.f);
                    float v10 = fmaxf(acc[i][j][2] + b0v, 0.f);
                    float v11 = fmaxf(acc[i][j][3] + b1v, 0.f);
                    esr[i][j][0] = v00; esr[i][j][1] = v01;
                    esr[i][j][2] = v10; esr[i][j][3] = v11;
                    float p0 = red4(v00 * sgs[r0 * 40 + 32 + e2] + v01 * sgs[r0 * 40 + 33 + e2]);
                    float p1 = red4(v10 * sgs[r1 * 40 + 32 + e2] + v11 * sgs[r1 * 40 + 33 + e2]);
                    if ((lane & 3) == 0) {
                        const int u = 8 * wn + j;
                        ssh[r0 * 16 + u] += p0;
                        ssh[r1 * 16 + u] += p1;
                    }
                }
            }
        } else {
#pragma unroll
            for (int i = 0; i < 2; i++) {
                const int r0 = 32 * wm + 16 * i + (lane >> 2), r1 = r0 + 8;
                const float* g0r = &sg[r0 * 68 + t * 16];
                const float* g1r = &sg[r1 * 68 + t * 16];
#pragma unroll
                for (int j = 0; j < 8; j++) {
                    const int ncl = 64 * wn + 8 * j + e2;
                    const float b0v = bias[n0 + ncl], b1v = bias[n0 + ncl + 1];
                    float v00 = fmaxf(acc[i][j][0] + b0v, 0.f);
                    float v01 = fmaxf(acc[i][j][1] + b1v, 0.f);
                    float v10 = fmaxf(acc[i][j][2] + b0v, 0.f);
                    float v11 = fmaxf(acc[i][j][3] + b1v, 0.f);
                    float pt0 = red4(v00 * g0r[e2] + v01 * g0r[e2 + 1]
                                   + esr[i][j][0] * g0r[8 + e2] + esr[i][j][1] * g0r[9 + e2]);
                    float pt1 = red4(v10 * g1r[e2] + v11 * g1r[e2 + 1]
                                   + esr[i][j][2] * g1r[8 + e2] + esr[i][j][3] * g1r[9 + e2]);
                    float ps0 = red4(v00 * sgs[r0 * 40 + t * 8 + e2] + v01 * sgs[r0 * 40 + t * 8 + e2 + 1]);
                    float ps1 = red4(v10 * sgs[r1 * 40 + t * 8 + e2] + v11 * sgs[r1 * 40 + t * 8 + e2 + 1]);
                    if ((lane & 3) == 0) {
                        const int u = 8 * wn + j;
                        stk[r0 * 16 + u] = pt0;
                        stk[r1 * 16 + u] = pt1;
                        ssh[r0 * 16 + u] += ps0;
                        ssh[r1 * 16 + u] += ps1;
                    }
                }
            }
            __syncthreads();
            for (int idx = tid; idx < 512; idx += 256) {
                const int r = idx >> 2, c4 = idx & 3;
                float4 tv = *(float4*)&stk[r * 16 + 4 * c4];
                const size_t off = ((size_t)t * B_ + m0 + r) * U_ + u0 + 4 * c4;
                *(float4*)&g_task0[off] = tv;
                store_a1(g_a1h, g_a1l, off, tv);
            }
        }
        __syncthreads();
    }

    // share -> a1 slot 4
    for (int idx = tid; idx < 512; idx += 256) {
        const int r = idx >> 2, c4 = idx & 3;
        float4 sv = *(float4*)&ssh[r * 16 + 4 * c4];
        const size_t off = ((size_t)4 * B_ + m0 + r) * U_ + u0 + 4 * c4;
        store_a1(g_a1h, g_a1l, off, sv);
    }
}

// ---------------------------------------------------------------------------
// Level-1 fused GEMM: writes final output directly.
// ---------------------------------------------------------------------------
__global__ __launch_bounds__(256, 1) void fgemm1(FGArgs args, float* __restrict__ out) {
    extern __shared__ __align__(128) char smem[];
    const uint32_t sb = smem_u32(smem);
    float* sg  = (float*)(smem + SM_SG);     // [128][68]
    float* stk = (float*)(smem + SM_STK1);   // [128][16]
    GEOM();

    for (int idx = tid; idx < 2048; idx += 256) {
        const int r = idx >> 4, c4 = idx & 15;
        const int tt = c4 >> 2, o = (c4 & 3) << 2;
        *(float4*)&sg[r * 68 + tt * 16 + o] =
            *(const float4*)&g_g1[((size_t)tt * B_ + m0 + r) * 16 + o];
    }
    __syncthreads();

    float esr[2][8][4];
    const int e2 = 2 * (lane & 3);

    const int order[5] = {4, 0, 1, 2, 3};
#pragma unroll 1
    for (int ti = 0; ti < 5; ti++) {
        const int t = order[ti];
        float acc[2][8][4];
#pragma unroll
        for (int i = 0; i < 2; i++)
#pragma unroll
            for (int j = 0; j < 8; j++)
#pragma unroll
                for (int q = 0; q < 4; q++) acc[i][j][q] = 0.f;

        kloop<U_>(g_a1h + ((size_t)t * B_ + m0) * U_, g_a1l + ((size_t)t * B_ + m0) * U_,
                  args.Bh[t] + (size_t)n0 * U_, args.Bl[t] + (size_t)n0 * U_,
                  sb, rlo, ch, dsw, aoff, boff, acc);

        const float* __restrict__ bias = args.bias[t];
        if (t == 4) {
#pragma unroll
            for (int i = 0; i < 2; i++)
#pragma unroll
                for (int j = 0; j < 8; j++) {
                    const int ncl = 64 * wn + 8 * j + e2;
                    const float b0v = bias[n0 + ncl], b1v = bias[n0 + ncl + 1];
                    esr[i][j][0] = fmaxf(acc[i][j][0] + b0v, 0.f);
                    esr[i][j][1] = fmaxf(acc[i][j][1] + b1v, 0.f);
                    esr[i][j][2] = fmaxf(acc[i][j][2] + b0v, 0.f);
                    esr[i][j][3] = fmaxf(acc[i][j][3] + b1v, 0.f);
                }
        } else {
#pragma unroll
            for (int i = 0; i < 2; i++) {
                const int r0 = 32 * wm + 16 * i + (lane >> 2), r1 = r0 + 8;
                const float* g0r = &sg[r0 * 68 + t * 16];
                const float* g1r = &sg[r1 * 68 + t * 16];
#pragma unroll
                for (int j = 0; j < 8; j++) {
                    const int ncl = 64 * wn + 8 * j + e2;
                    const float b0v = bias[n0 + ncl], b1v = bias[n0 + ncl + 1];
                    float v00 = fmaxf(acc[i][j][0] + b0v, 0.f);
                    float v01 = fmaxf(acc[i][j][1] + b1v, 0.f);
                    float v10 = fmaxf(acc[i][j][2] + b0v, 0.f);
                    float v11 = fmaxf(acc[i][j][3] + b1v, 0.f);
                    float pt0 = red4(v00 * g0r[e2] + v01 * g0r[e2 + 1]
                                   + esr[i][j][0] * g0r[8 + e2] + esr[i][j][1] * g0r[9 + e2]);
                    float pt1 = red4(v10 * g1r[e2] + v11 * g1r[e2 + 1]
                                   + esr[i][j][2] * g1r[8 + e2] + esr[i][j][3] * g1r[9 + e2]);
                    if ((lane & 3) == 0) {
                        const int u = 8 * wn + j;
                        stk[r0 * 16 + u] = pt0;
                        stk[r1 * 16 + u] = pt1;
                    }
                }
            }
            __syncthreads();
            for (int idx = tid; idx < 512; idx += 256) {
                const int r = idx >> 2, c4 = idx & 3;
                float4 tv = *(float4*)&stk[r * 16 + 4 * c4];
                *(float4*)&out[((size_t)t * B_ + m0 + r) * U_ + u0 + 4 * c4] = tv;
            }
        }
        __syncthreads();
    }
}

// ---------------------------------------------------------------------------
// gates0 / gates1 (R8 fast versions, unchanged)
// ---------------------------------------------------------------------------
__global__ __launch_bounds__(256) void gates0(const float* __restrict__ x,
                                              const float* __restrict__ gw0,
                                              const float* __restrict__ gb0,
                                              const float* __restrict__ gws,
                                              const float* __restrict__ gbs) {
    const int b0 = blockIdx.x * 16;
    const int tid = threadIdx.x;
    __shared__ float sx[16][128];
    __shared__ float sz[16][104];

    const bool active = tid < 208;
    const int rh = (tid >= 104) ? 1 : 0;
    const int c  = active ? (tid - rh * 104) : 0;

    const float* Wp; int wstride;
    if (c < 64) { Wp = gw0 + (size_t)(c >> 4) * D_ * 16 + (c & 15); wstride = 16; }
    else        { Wp = gws + (c - 64);                              wstride = 40; }

    float acc[8];
#pragma unroll
    for (int r = 0; r < 8; r++) acc[r] = 0.f;

    for (int kc = 0; kc < D_ / 128; kc++) {
        __syncthreads();
#pragma unroll
        for (int p = 0; p < 2; p++) {
            const int idx = tid + p * 256;
            const int row = idx >> 5, c4 = idx & 31;
            *(float4*)&sx[row][c4 * 4] =
                *(const float4*)(x + (size_t)(b0 + row) * D_ + kc * 128 + c4 * 4);
        }
        __syncthreads();
        if (active) {
            const float* wp = Wp + (size_t)kc * 128 * wstride;
#pragma unroll 4
            for (int k = 0; k < 128; k += 4) {
                const float w0 = wp[(k + 0) * wstride];
                const float w1 = wp[(k + 1) * wstride];
                const float w2 = wp[(k + 2) * wstride];
                const float w3 = wp[(k + 3) * wstride];
#pragma unroll
                for (int r = 0; r < 8; r++) {
                    float4 xv = *(const float4*)&sx[rh * 8 + r][k];
                    acc[r] += xv.x * w0 + xv.y * w1 + xv.z * w2 + xv.w * w3;
                }
            }
        }
    }
    if (active) {
        const float bb = (c < 64) ? gb0[c] : gbs[c - 64];
#pragma unroll
        for (int r = 0; r < 8; r++) sz[rh * 8 + r][c] = acc[r] + bb;
    }
    __syncthreads();

    if (tid < 80) {
        const int r = tid & 15, g = tid >> 4;
        const int base = (g < 4) ? g * 16 : 64;
        const int len  = (g < 4) ? 16 : 40;
        float mx = -1e30f;
        for (int i = 0; i < len; i++) mx = fmaxf(mx, sz[r][base + i]);
        float s = 0.f;
        for (int i = 0; i < len; i++) s += expf(sz[r][base + i] - mx);
        const float inv = 1.f / s;
        if (g < 4) {
            float* o = g_g0 + ((size_t)g * B_ + b0 + r) * 16;
            for (int i = 0; i < 16; i++) o[i] = expf(sz[r][base + i] - mx) * inv;
        } else {
            float* o = g_gs + (size_t)(b0 + r) * 40;
            for (int i = 0; i < 40; i++) o[i] = expf(sz[r][base + i] - mx) * inv;
        }
    }
}

__global__ __launch_bounds__(256) void gates1(const float* __restrict__ gw1,
                                              const float* __restrict__ gb1) {
    const int b0 = blockIdx.x * 16;
    const int tid = threadIdx.x;
    __shared__ float s1[4][16][128];
    __shared__ float sz[16][64];

    const bool active = tid < 128;
    const int rh = (tid >> 6) & 1;
    const int c  = tid & 63;
    const int tt = c >> 4;
    const float* Wp = gw1 + (size_t)tt * U_ * 16 + (c & 15);

    float acc[8];
#pragma unroll
    for (int r = 0; r < 8; r++) acc[r] = 0.f;

    for (int kc = 0; kc < U_ / 128; kc++) {
        __syncthreads();
#pragma unroll
        for (int p = 0; p < 8; p++) {
            const int idx = tid + p * 256;
            const int tz = idx >> 9, row = (idx >> 5) & 15, c4 = idx & 31;
            *(float4*)&s1[tz][row][c4 * 4] =
                *(const float4*)(g_task0 + ((size_t)tz * B_ + b0 + row) * U_ + kc * 128 + c4 * 4);
        }
        __syncthreads();
        if (active) {
            const float* wp = Wp + (size_t)kc * 128 * 16;
#pragma unroll 4
            for (int k = 0; k < 128; k += 4) {
                const float w0 = wp[(k + 0) * 16];
                const float w1 = wp[(k + 1) * 16];
                const float w2 = wp[(k + 2) * 16];
                const float w3 = wp[(k + 3) * 16];
#pragma unroll
                for (int r = 0; r < 8; r++) {
                    float4 xv = *(const float4*)&s1[tt][rh * 8 + r][k];
                    acc[r] += xv.x * w0 + xv.y * w1 + xv.z * w2 + xv.w * w3;
                }
            }
        }
    }
    if (active) {
        const float bb = gb1[c];
#pragma unroll
        for (int r = 0; r < 8; r++) sz[rh * 8 + r][c] = acc[r] + bb;
    }
    __syncthreads();

    if (tid < 64) {
        const int r = tid & 15, g = tid >> 4;
        float mx = -1e30f;
        for (int i = 0; i < 16; i++) mx = fmaxf(mx, sz[r][g * 16 + i]);
        float s = 0.f;
        for (int i = 0; i < 16; i++) s += expf(sz[r][g * 16 + i] - mx);
        const float inv = 1.f / s;
        float* o = g_g1 + ((size_t)g * B_ + b0 + r) * 16;
        for (int i = 0; i < 16; i++) o[i] = expf(sz[r][g * 16 + i] - mx) * inv;
    }
}

// ---------------------------------------------------------------------------
// Launch
// ---------------------------------------------------------------------------
extern "C" void kernel_launch(void* const* d_in, const int* in_sizes, int n_in,
                              void* d_out, int out_size) {
    (void)in_sizes; (void)n_in; (void)out_size;
    const float* x    = (const float*)d_in[0];
    const float* ews0 = (const float*)d_in[1];
    const float* ebs0 = (const float*)d_in[2];
    const float* ews1 = (const float*)d_in[3];
    const float* ebs1 = (const float*)d_in[4];
    const float* gws  = (const float*)d_in[5];
    const float* gbs  = (const float*)d_in[6];
    const float* ew0  = (const float*)d_in[7];
    const float* eb0  = (const float*)d_in[8];
    const float* gw0  = (const float*)d_in[9];
    const float* gb0  = (const float*)d_in[10];
    const float* ew1  = (const float*)d_in[11];
    const float* eb1  = (const float*)d_in[12];
    const float* gw1  = (const float*)d_in[13];
    const float* gb1  = (const float*)d_in[14];

    cudaFuncSetAttribute(fgemm0, cudaFuncAttributeMaxDynamicSharedMemorySize, SMEM0);
    cudaFuncSetAttribute(fgemm1, cudaFuncAttributeMaxDynamicSharedMemorySize, SMEM1);

    __nv_bfloat16 *xhi, *xlo, *bt0h, *bt0l, *bt1h, *bt1l;
    cudaGetSymbolAddress((void**)&xhi,  g_xhi);
    cudaGetSymbolAddress((void**)&xlo,  g_xlo);
    cudaGetSymbolAddress((void**)&bt0h, g_bt0h);
    cudaGetSymbolAddress((void**)&bt0l, g_bt0l);
    cudaGetSymbolAddress((void**)&bt1h, g_bt1h);
    cudaGetSymbolAddress((void**)&bt1l, g_bt1l);

    // conversions
    convX<<<(B_ * D_ / 4) / 256, 256>>>(x, xhi, xlo);
    ConvBArgs cb0;
    for (int t = 0; t < 4; t++) cb0.src[t] = ew0 + (size_t)t * D_ * UE;
    cb0.src[4] = ews0; cb0.hi = bt0h; cb0.lo = bt0l; cb0.K = D_;
    convB<<<dim3(NTOT / 32, D_ / 32, 5), dim3(32, 8)>>>(cb0);
    ConvBArgs cb1;
    for (int t = 0; t < 4; t++) cb1.src[t] = ew1 + (size_t)t * U_ * UE;
    cb1.src[4] = ews1; cb1.hi = bt1h; cb1.lo = bt1l; cb1.K = U_;
    convB<<<dim3(NTOT / 32, U_ / 32, 5), dim3(32, 8)>>>(cb1);

    // level 0
    gates0<<<B_ / 16, 256>>>(x, gw0, gb0, gws, gbs);
    FGArgs a0;
    for (int t = 0; t < 5; t++) {
        a0.Bh[t] = bt0h + (size_t)t * NTOT * D_;
        a0.Bl[t] = bt0l + (size_t)t * NTOT * D_;
    }
    for (int t = 0; t < 4; t++) a0.bias[t] = eb0 + (size_t)t * UE;
    a0.bias[4] = ebs0;
    fgemm0<<<2048, 256, SMEM0>>>(a0);

    // level 1
    gates1<<<B_ / 16, 256>>>(gw1, gb1);
    FGArgs a1;
    for (int t = 0; t < 5; t++) {
        a1.Bh[t] = bt1h + (size_t)t * NTOT * U_;
        a1.Bl[t] = bt1l + (size_t)t * NTOT * U_;
    }
    for (int t = 0; t < 4; t++) a1.bias[t] = eb1 + (size_t)t * UE;
    a1.bias[4] = ebs1;
    fgemm1<<<2048, 256, SMEM1>>>(a1, (float*)d_out);
}

// round 12
// speedup vs baseline: 2.5904x; 1.1701x over previous
#include <cuda_runtime.h>
#include <cuda_bf16.h>
#include <cstdint>

#define T_  4
#define B_  8192
#define D_  1024
#define U_  512
#define UE  4096
#define NTOT 4096

// ---------------------------------------------------------------------------
// Device scratch
// ---------------------------------------------------------------------------
__device__ float g_Hs[(size_t)B_ * UE];              // shared-expert outputs (reused per level)
__device__ __nv_bfloat16 g_xhi[(size_t)B_ * D_];
__device__ __nv_bfloat16 g_xlo[(size_t)B_ * D_];
__device__ __nv_bfloat16 g_bt0h[5ull * NTOT * D_];   // level-0 B^T hi (N-major)
__device__ __nv_bfloat16 g_bt0l[5ull * NTOT * D_];
__device__ __nv_bfloat16 g_bt1h[5ull * NTOT * U_];
__device__ __nv_bfloat16 g_bt1l[5ull * NTOT * U_];
__device__ __nv_bfloat16 g_a1h[5ull * B_ * U_];      // level-1 A (4 tasks + share)
__device__ __nv_bfloat16 g_a1l[5ull * B_ * U_];
__device__ float g_g0[(size_t)T_ * B_ * 16];
__device__ float g_gs[(size_t)B_ * 40];
__device__ float g_task0[(size_t)T_ * B_ * U_];      // fp32 (gates1 input)
__device__ float g_g1[(size_t)T_ * B_ * 16];

// ---------------------------------------------------------------------------
// PTX helpers (baseline sm_80+ only)
// ---------------------------------------------------------------------------
__device__ __forceinline__ uint32_t smem_u32(const void* p) {
    uint32_t a;
    asm("{ .reg .u64 t; cvta.to.shared.u64 t, %1; cvt.u32.u64 %0, t; }" : "=r"(a) : "l"(p));
    return a;
}
__device__ __forceinline__ void cp16(uint32_t dst, const void* src) {
    asm volatile("cp.async.cg.shared.global [%0], [%1], 16;" :: "r"(dst), "l"(src));
}
__device__ __forceinline__ void ldsm4(uint32_t* r, uint32_t addr) {
    asm volatile("ldmatrix.sync.aligned.m8n8.x4.shared.b16 {%0,%1,%2,%3}, [%4];"
        : "=r"(r[0]), "=r"(r[1]), "=r"(r[2]), "=r"(r[3]) : "r"(addr));
}
__device__ __forceinline__ void mma16816(float* c, const uint32_t* a, uint32_t b0, uint32_t b1) {
    asm volatile("mma.sync.aligned.m16n8k16.row.col.f32.bf16.bf16.f32 "
        "{%0,%1,%2,%3}, {%4,%5,%6,%7}, {%8,%9}, {%0,%1,%2,%3};"
        : "+f"(c[0]), "+f"(c[1]), "+f"(c[2]), "+f"(c[3])
        : "r"(a[0]), "r"(a[1]), "r"(a[2]), "r"(a[3]), "r"(b0), "r"(b1));
}
__device__ __forceinline__ float red4(float p) {
    p += __shfl_xor_sync(0xffffffffu, p, 1);
    p += __shfl_xor_sync(0xffffffffu, p, 2);
    return p;
}
__device__ __forceinline__ void store_a1(__nv_bfloat16* h, __nv_bfloat16* l,
                                         size_t off, float4 v) {
    __nv_bfloat16 h0 = __float2bfloat16(v.x), h1 = __float2bfloat16(v.y);
    __nv_bfloat16 h2 = __float2bfloat16(v.z), h3 = __float2bfloat16(v.w);
    *(__nv_bfloat162*)&h[off]     = __nv_bfloat162(h0, h1);
    *(__nv_bfloat162*)&h[off + 2] = __nv_bfloat162(h2, h3);
    *(__nv_bfloat162*)&l[off] = __nv_bfloat162(
        __float2bfloat16(v.x - __bfloat162float(h0)),
        __float2bfloat16(v.y - __bfloat162float(h1)));
    *(__nv_bfloat162*)&l[off + 2] = __nv_bfloat162(
        __float2bfloat16(v.z - __bfloat162float(h2)),
        __float2bfloat16(v.w - __bfloat162float(h3)));
}

// ---------------------------------------------------------------------------
// Conversions (fp32 -> bf16 hi/lo; B transposed to N-major)
// ---------------------------------------------------------------------------
__global__ void convX(const float* __restrict__ x, __nv_bfloat16* __restrict__ hi,
                      __nv_bfloat16* __restrict__ lo) {
    size_t i = (size_t)blockIdx.x * blockDim.x + threadIdx.x;
    float4 v = ((const float4*)x)[i];
    store_a1(hi, lo, 4 * i, v);
}

struct ConvBArgs { const float* src[5]; __nv_bfloat16* hi; __nv_bfloat16* lo; int K; };

__global__ void convB(ConvBArgs a) {
    __shared__ float s[32][33];
    const int z = blockIdx.z;
    const float* __restrict__ src = a.src[z];
    const int n0 = blockIdx.x * 32, k0 = blockIdx.y * 32;
    const int tx = threadIdx.x, ty = threadIdx.y;
#pragma unroll
    for (int i = 0; i < 4; i++)
        s[ty + i * 8][tx] = src[(size_t)(k0 + ty + i * 8) * UE + n0 + tx];
    __syncthreads();
    __nv_bfloat16* oh = a.hi + (size_t)z * NTOT * a.K;
    __nv_bfloat16* ol = a.lo + (size_t)z * NTOT * a.K;
#pragma unroll
    for (int i = 0; i < 4; i++) {
        const int n = n0 + ty + i * 8, k = k0 + tx;
        float v = s[tx][ty + i * 8];
        __nv_bfloat16 h = __float2bfloat16(v);
        oh[(size_t)n * a.K + k] = h;
        ol[(size_t)n * a.K + k] = __float2bfloat16(v - __bfloat162float(h));
    }
}

// ---------------------------------------------------------------------------
// GEMM machinery: 128x128 tile, K-step 32, 3-stage cp.async (R8-proven
// schedule: prologue 2 stages, prefetch c+2), 8 warps.
// ---------------------------------------------------------------------------
#define MAT_BYTES 8192
#define STAGE_BYTES (4 * MAT_BYTES)         // 32 KB
#define SMEM_S  (3 * STAGE_BYTES)           // 96 KB (share kernel)
#define SM_STK  (3 * STAGE_BYTES)           // staging float[128][16]
#define SM_SSH  (SM_STK + 8192)
#define SMEM_B0 (SM_SSH + 8192)             // 112 KB
#define SMEM_B1 (SM_STK + 8192)             // 104 KB

template<int KK>
__device__ __forceinline__ void kloop(const __nv_bfloat16* __restrict__ A_h,
                                      const __nv_bfloat16* __restrict__ A_l,
                                      const __nv_bfloat16* __restrict__ B_h,
                                      const __nv_bfloat16* __restrict__ B_l,
                                      uint32_t sb, int rlo, int ch, int dsw,
                                      const uint32_t (&aoff)[2][2],
                                      const uint32_t (&boff)[4][2],
                                      float (&acc)[2][8][4]) {
    constexpr int nk = KK / 32;
    const __nv_bfloat16* srcs[4] = { A_h, A_l, B_h, B_l };
    auto load_stage = [&](int buf, int kc) {
        const uint32_t base = sb + (uint32_t)buf * STAGE_BYTES;
#pragma unroll
        for (int i = 0; i < 8; i++) {
            const int mat = i >> 1;
            const int r   = ((i & 1) << 6) + rlo;
            cp16(base + mat * MAT_BYTES + r * 64 + dsw,
                 srcs[mat] + (size_t)r * KK + kc + ch * 8);
        }
        asm volatile("cp.async.commit_group;" ::: "memory");
    };
    // R8-proven schedule: 2 stages in flight, 3 buffers.
    load_stage(0, 0);
    load_stage(1, 32);
    int cb = 0;   // compute buffer = c mod 3
    for (int c = 0; c < nk; c++) {
        if (c + 1 < nk) asm volatile("cp.async.wait_group 1;" ::: "memory");
        else            asm volatile("cp.async.wait_group 0;" ::: "memory");
        __syncthreads();
        if (c + 2 < nk) {
            int nb = cb + 2; if (nb >= 3) nb -= 3;   // (c+2) mod 3
            load_stage(nb, (c + 2) * 32);
        }
        const uint32_t st = sb + (uint32_t)cb * STAGE_BYTES;
        if (++cb == 3) cb = 0;
#pragma unroll
        for (int ks = 0; ks < 2; ks++) {
            uint32_t ahi[2][4], alo[2][4];
#pragma unroll
            for (int i = 0; i < 2; i++) {
                ldsm4(ahi[i], st + aoff[i][ks]);
                ldsm4(alo[i], st + MAT_BYTES + aoff[i][ks]);
            }
            uint32_t bf[4][4];
#pragma unroll
            for (int j = 0; j < 4; j++) ldsm4(bf[j], st + 2 * MAT_BYTES + boff[j][ks]);
#pragma unroll
            for (int i = 0; i < 2; i++)
#pragma unroll
                for (int j = 0; j < 4; j++) {
                    mma16816(acc[i][2 * j],     ahi[i], bf[j][0], bf[j][2]);
                    mma16816(acc[i][2 * j + 1], ahi[i], bf[j][1], bf[j][3]);
                    mma16816(acc[i][2 * j],     alo[i], bf[j][0], bf[j][2]);
                    mma16816(acc[i][2 * j + 1], alo[i], bf[j][1], bf[j][3]);
                }
#pragma unroll
            for (int j = 0; j < 4; j++) ldsm4(bf[j], st + 3 * MAT_BYTES + boff[j][ks]);
#pragma unroll
            for (int i = 0; i < 2; i++)
#pragma unroll
                for (int j = 0; j < 4; j++) {
                    mma16816(acc[i][2 * j],     ahi[i], bf[j][0], bf[j][2]);
                    mma16816(acc[i][2 * j + 1], ahi[i], bf[j][1], bf[j][3]);
                }
        }
    }
}

#define GEOM() \
    const int id = blockIdx.x; \
    const int nt = (id >> 4) & 31; \
    const int mt = (id & 15) + ((id >> 9) << 4); \
    const int n0 = nt << 7, m0 = mt << 7; \
    const int u0 = nt << 4; (void)u0; \
    const int tid = threadIdx.x; \
    const int lane = tid & 31; \
    const int w = tid >> 5, wm = w & 3, wn = w >> 2, hb = lane >> 4; \
    const int rlo = tid >> 2, ch = tid & 3; \
    const int dsw = ((ch ^ ((rlo >> 1) & 3)) << 4); \
    uint32_t aoff[2][2], boff[4][2]; \
    _Pragma("unroll") for (int i = 0; i < 2; i++) { \
        const int rA = 32 * wm + 16 * i + (lane & 15); \
        const int csw = (rA >> 1) & 3; \
        _Pragma("unroll") for (int ks = 0; ks < 2; ks++) \
            aoff[i][ks] = (uint32_t)(rA * 64 + (((2 * ks + hb) ^ csw) << 4)); \
    } \
    _Pragma("unroll") for (int j = 0; j < 4; j++) { \
        const int rB = 64 * wn + 16 * j + (((lane >> 3) & 1) << 3) + (lane & 7); \
        const int csw = (rB >> 1) & 3; \
        _Pragma("unroll") for (int ks = 0; ks < 2; ks++) \
            boff[j][ks] = (uint32_t)(rB * 64 + (((2 * ks + hb) ^ csw) << 4)); \
    }

#define ZERO_ACC() \
    float acc[2][8][4]; \
    _Pragma("unroll") for (int i = 0; i < 2; i++) \
        _Pragma("unroll") for (int j = 0; j < 8; j++) \
            _Pragma("unroll") for (int q = 0; q < 4; q++) acc[i][j][q] = 0.f;

// ---------------------------------------------------------------------------
// Share-expert GEMM: Hs = relu(A @ B + bias), plain tile writeback.
// ---------------------------------------------------------------------------
template<int KK>
__global__ __launch_bounds__(256, 2) void fgemmS(const __nv_bfloat16* __restrict__ Ah,
                                                 const __nv_bfloat16* __restrict__ Al,
                                                 const __nv_bfloat16* __restrict__ Bh,
                                                 const __nv_bfloat16* __restrict__ Bl,
                                                 const float* __restrict__ bias) {
    extern __shared__ __align__(128) char smem[];
    const uint32_t sb = smem_u32(smem);
    GEOM();
    ZERO_ACC();
    kloop<KK>(Ah + (size_t)m0 * KK, Al + (size_t)m0 * KK,
              Bh + (size_t)n0 * KK, Bl + (size_t)n0 * KK,
              sb, rlo, ch, dsw, aoff, boff, acc);
    const int e2 = 2 * (lane & 3);
#pragma unroll
    for (int i = 0; i < 2; i++) {
        const int mr = m0 + 32 * wm + 16 * i + (lane >> 2);
#pragma unroll
        for (int j = 0; j < 8; j++) {
            const int nc = n0 + 64 * wn + 8 * j + e2;
            const float b0v = bias[nc], b1v = bias[nc + 1];
            float2 o0, o1;
            o0.x = fmaxf(acc[i][j][0] + b0v, 0.f);
            o0.y = fmaxf(acc[i][j][1] + b1v, 0.f);
            o1.x = fmaxf(acc[i][j][2] + b0v, 0.f);
            o1.y = fmaxf(acc[i][j][3] + b1v, 0.f);
            *(float2*)(g_Hs + (size_t)mr * UE + nc)       = o0;
            *(float2*)(g_Hs + (size_t)(mr + 8) * UE + nc) = o1;
        }
    }
}

struct FGArgs {
    const __nv_bfloat16 *Bh[4], *Bl[4];
    const float* bias[4];
};

// ---------------------------------------------------------------------------
// Level-0 fused task GEMM: loops t=0..3; epilogue combines gates + es (gmem),
// writes task0 fp32 + a1 bf16 (tasks and share).
// ---------------------------------------------------------------------------
__global__ __launch_bounds__(256, 2) void fgemmB0(FGArgs args) {
    extern __shared__ __align__(128) char smem[];
    const uint32_t sb = smem_u32(smem);
    float* stk = (float*)(smem + SM_STK);
    float* ssh = (float*)(smem + SM_SSH);
    GEOM();
    for (int idx = tid; idx < 2048; idx += 256) ssh[idx] = 0.f;

    const __nv_bfloat16* Ah = g_xhi + (size_t)m0 * D_;
    const __nv_bfloat16* Al = g_xlo + (size_t)m0 * D_;
    const int e2 = 2 * (lane & 3);

#pragma unroll 1
    for (int t = 0; t < 4; t++) {
        ZERO_ACC();
        kloop<D_>(Ah, Al, args.Bh[t] + (size_t)n0 * D_, args.Bl[t] + (size_t)n0 * D_,
                  sb, rlo, ch, dsw, aoff, boff, acc);

        const float* __restrict__ bias = args.bias[t];
#pragma unroll
        for (int i = 0; i < 2; i++) {
            const int r0 = 32 * wm + 16 * i + (lane >> 2), r1 = r0 + 8;
            const float2 ga0 = *(const float2*)&g_g0[((size_t)t * B_ + m0 + r0) * 16 + e2];
            const float2 gb0 = *(const float2*)&g_g0[((size_t)t * B_ + m0 + r0) * 16 + 8 + e2];
            const float2 ga1 = *(const float2*)&g_g0[((size_t)t * B_ + m0 + r1) * 16 + e2];
            const float2 gb1 = *(const float2*)&g_g0[((size_t)t * B_ + m0 + r1) * 16 + 8 + e2];
            const float2 gt0 = *(const float2*)&g_gs[(size_t)(m0 + r0) * 40 + t * 8 + e2];
            const float2 gt1 = *(const float2*)&g_gs[(size_t)(m0 + r1) * 40 + t * 8 + e2];
            float2 gq0 = {0.f, 0.f}, gq1 = {0.f, 0.f};
            if (t == 3) {
                gq0 = *(const float2*)&g_gs[(size_t)(m0 + r0) * 40 + 32 + e2];
                gq1 = *(const float2*)&g_gs[(size_t)(m0 + r1) * 40 + 32 + e2];
            }
#pragma unroll
            for (int j = 0; j < 8; j++) {
                const int ncl = 64 * wn + 8 * j + e2;
                const float b0v = bias[n0 + ncl], b1v = bias[n0 + ncl + 1];
                const float v00 = fmaxf(acc[i][j][0] + b0v, 0.f);
                const float v01 = fmaxf(acc[i][j][1] + b1v, 0.f);
                const float v10 = fmaxf(acc[i][j][2] + b0v, 0.f);
                const float v11 = fmaxf(acc[i][j][3] + b1v, 0.f);
                const float2 es0 = *(const float2*)&g_Hs[(size_t)(m0 + r0) * UE + n0 + ncl];
                const float2 es1 = *(const float2*)&g_Hs[(size_t)(m0 + r1) * UE + n0 + ncl];
                float pt0 = red4(v00 * ga0.x + v01 * ga0.y + es0.x * gb0.x + es0.y * gb0.y);
                float pt1 = red4(v10 * ga1.x + v11 * ga1.y + es1.x * gb1.x + es1.y * gb1.y);
                float ps0 = v00 * gt0.x + v01 * gt0.y;
                float ps1 = v10 * gt1.x + v11 * gt1.y;
                if (t == 3) {
                    ps0 += es0.x * gq0.x + es0.y * gq0.y;
                    ps1 += es1.x * gq1.x + es1.y * gq1.y;
                }
                ps0 = red4(ps0); ps1 = red4(ps1);
                if ((lane & 3) == 0) {
                    const int u = 8 * wn + j;
                    stk[r0 * 16 + u] = pt0;
                    stk[r1 * 16 + u] = pt1;
                    ssh[r0 * 16 + u] += ps0;
                    ssh[r1 * 16 + u] += ps1;
                }
            }
        }
        __syncthreads();
        for (int idx = tid; idx < 512; idx += 256) {
            const int r = idx >> 2, c4 = idx & 3;
            float4 tv = *(float4*)&stk[r * 16 + 4 * c4];
            const size_t off = ((size_t)t * B_ + m0 + r) * U_ + u0 + 4 * c4;
            *(float4*)&g_task0[off] = tv;
            store_a1(g_a1h, g_a1l, off, tv);
        }
        __syncthreads();
    }

    for (int idx = tid; idx < 512; idx += 256) {
        const int r = idx >> 2, c4 = idx & 3;
        float4 sv = *(float4*)&ssh[r * 16 + 4 * c4];
        store_a1(g_a1h, g_a1l, ((size_t)4 * B_ + m0 + r) * U_ + u0 + 4 * c4, sv);
    }
}

// ---------------------------------------------------------------------------
// Level-1 fused task GEMM: writes final out directly.
// ---------------------------------------------------------------------------
__global__ __launch_bounds__(256, 2) void fgemmB1(FGArgs args, float* __restrict__ out) {
    extern __shared__ __align__(128) char smem[];
    const uint32_t sb = smem_u32(smem);
    float* stk = (float*)(smem + SM_STK);
    GEOM();
    const int e2 = 2 * (lane & 3);

#pragma unroll 1
    for (int t = 0; t < 4; t++) {
        ZERO_ACC();
        kloop<U_>(g_a1h + ((size_t)t * B_ + m0) * U_, g_a1l + ((size_t)t * B_ + m0) * U_,
                  args.Bh[t] + (size_t)n0 * U_, args.Bl[t] + (size_t)n0 * U_,
                  sb, rlo, ch, dsw, aoff, boff, acc);

        const float* __restrict__ bias = args.bias[t];
#pragma unroll
        for (int i = 0; i < 2; i++) {
            const int r0 = 32 * wm + 16 * i + (lane >> 2), r1 = r0 + 8;
            const float2 ga0 = *(const float2*)&g_g1[((size_t)t * B_ + m0 + r0) * 16 + e2];
            const float2 gb0 = *(const float2*)&g_g1[((size_t)t * B_ + m0 + r0) * 16 + 8 + e2];
            const float2 ga1 = *(const float2*)&g_g1[((size_t)t * B_ + m0 + r1) * 16 + e2];
            const float2 gb1 = *(const float2*)&g_g1[((size_t)t * B_ + m0 + r1) * 16 + 8 + e2];
#pragma unroll
            for (int j = 0; j < 8; j++) {
                const int ncl = 64 * wn + 8 * j + e2;
                const float b0v = bias[n0 + ncl], b1v = bias[n0 + ncl + 1];
                const float v00 = fmaxf(acc[i][j][0] + b0v, 0.f);
                const float v01 = fmaxf(acc[i][j][1] + b1v, 0.f);
                const float v10 = fmaxf(acc[i][j][2] + b0v, 0.f);
                const float v11 = fmaxf(acc[i][j][3] + b1v, 0.f);
                const float2 es0 = *(const float2*)&g_Hs[(size_t)(m0 + r0) * UE + n0 + ncl];
                const float2 es1 = *(const float2*)&g_Hs[(size_t)(m0 + r1) * UE + n0 + ncl];
                float pt0 = red4(v00 * ga0.x + v01 * ga0.y + es0.x * gb0.x + es0.y * gb0.y);
                float pt1 = red4(v10 * ga1.x + v11 * ga1.y + es1.x * gb1.x + es1.y * gb1.y);
                if ((lane & 3) == 0) {
                    const int u = 8 * wn + j;
                    stk[r0 * 16 + u] = pt0;
                    stk[r1 * 16 + u] = pt1;
                }
            }
        }
        __syncthreads();
        for (int idx = tid; idx < 512; idx += 256) {
            const int r = idx >> 2, c4 = idx & 3;
            float4 tv = *(float4*)&stk[r * 16 + 4 * c4];
            *(float4*)&out[((size_t)t * B_ + m0 + r) * U_ + u0 + 4 * c4] = tv;
        }
        __syncthreads();
    }
}

// ---------------------------------------------------------------------------
// gates0 / gates1 (R8 fast versions, unchanged)
// ---------------------------------------------------------------------------
__global__ __launch_bounds__(256) void gates0(const float* __restrict__ x,
                                              const float* __restrict__ gw0,
                                              const float* __restrict__ gb0,
                                              const float* __restrict__ gws,
                                              const float* __restrict__ gbs) {
    const int b0 = blockIdx.x * 16;
    const int tid = threadIdx.x;
    __shared__ float sx[16][128];
    __shared__ float sz[16][104];

    const bool active = tid < 208;
    const int rh = (tid >= 104) ? 1 : 0;
    const int c  = active ? (tid - rh * 104) : 0;

    const float* Wp; int wstride;
    if (c < 64) { Wp = gw0 + (size_t)(c >> 4) * D_ * 16 + (c & 15); wstride = 16; }
    else        { Wp = gws + (c - 64);                              wstride = 40; }

    float acc[8];
#pragma unroll
    for (int r = 0; r < 8; r++) acc[r] = 0.f;

    for (int kc = 0; kc < D_ / 128; kc++) {
        __syncthreads();
#pragma unroll
        for (int p = 0; p < 2; p++) {
            const int idx = tid + p * 256;
            const int row = idx >> 5, c4 = idx & 31;
            *(float4*)&sx[row][c4 * 4] =
                *(const float4*)(x + (size_t)(b0 + row) * D_ + kc * 128 + c4 * 4);
        }
        __syncthreads();
        if (active) {
            const float* wp = Wp + (size_t)kc * 128 * wstride;
#pragma unroll 4
            for (int k = 0; k < 128; k += 4) {
                const float w0 = wp[(k + 0) * wstride];
                const float w1 = wp[(k + 1) * wstride];
                const float w2 = wp[(k + 2) * wstride];
                const float w3 = wp[(k + 3) * wstride];
#pragma unroll
                for (int r = 0; r < 8; r++) {
                    float4 xv = *(const float4*)&sx[rh * 8 + r][k];
                    acc[r] += xv.x * w0 + xv.y * w1 + xv.z * w2 + xv.w * w3;
                }
            }
        }
    }
    if (active) {
        const float bb = (c < 64) ? gb0[c] : gbs[c - 64];
#pragma unroll
        for (int r = 0; r < 8; r++) sz[rh * 8 + r][c] = acc[r] + bb;
    }
    __syncthreads();

    if (tid < 80) {
        const int r = tid & 15, g = tid >> 4;
        const int base = (g < 4) ? g * 16 : 64;
        const int len  = (g < 4) ? 16 : 40;
        float mx = -1e30f;
        for (int i = 0; i < len; i++) mx = fmaxf(mx, sz[r][base + i]);
        float s = 0.f;
        for (int i = 0; i < len; i++) s += expf(sz[r][base + i] - mx);
        const float inv = 1.f / s;
        if (g < 4) {
            float* o = g_g0 + ((size_t)g * B_ + b0 + r) * 16;
            for (int i = 0; i < 16; i++) o[i] = expf(sz[r][base + i] - mx) * inv;
        } else {
            float* o = g_gs + (size_t)(b0 + r) * 40;
            for (int i = 0; i < 40; i++) o[i] = expf(sz[r][base + i] - mx) * inv;
        }
    }
}

__global__ __launch_bounds__(256) void gates1(const float* __restrict__ gw1,
                                              const float* __restrict__ gb1) {
    const int b0 = blockIdx.x * 16;
    const int tid = threadIdx.x;
    __shared__ float s1[4][16][128];
    __shared__ float sz[16][64];

    const bool active = tid < 128;
    const int rh = (tid >> 6) & 1;
    const int c  = tid & 63;
    const int tt = c >> 4;
    const float* Wp = gw1 + (size_t)tt * U_ * 16 + (c & 15);

    float acc[8];
#pragma unroll
    for (int r = 0; r < 8; r++) acc[r] = 0.f;

    for (int kc = 0; kc < U_ / 128; kc++) {
        __syncthreads();
#pragma unroll
        for (int p = 0; p < 8; p++) {
            const int idx = tid + p * 256;
            const int tz = idx >> 9, row = (idx >> 5) & 15, c4 = idx & 31;
            *(float4*)&s1[tz][row][c4 * 4] =
                *(const float4*)(g_task0 + ((size_t)tz * B_ + b0 + row) * U_ + kc * 128 + c4 * 4);
        }
        __syncthreads();
        if (active) {
            const float* wp = Wp + (size_t)kc * 128 * 16;
#pragma unroll 4
            for (int k = 0; k < 128; k += 4) {
                const float w0 = wp[(k + 0) * 16];
                const float w1 = wp[(k + 1) * 16];
                const float w2 = wp[(k + 2) * 16];
                const float w3 = wp[(k + 3) * 16];
#pragma unroll
                for (int r = 0; r < 8; r++) {
                    float4 xv = *(const float4*)&s1[tt][rh * 8 + r][k];
                    acc[r] += xv.x * w0 + xv.y * w1 + xv.z * w2 + xv.w * w3;
                }
            }
        }
    }
    if (active) {
        const float bb = gb1[c];
#pragma unroll
        for (int r = 0; r < 8; r++) sz[rh * 8 + r][c] = acc[r] + bb;
    }
    __syncthreads();

    if (tid < 64) {
        const int r = tid & 15, g = tid >> 4;
        float mx = -1e30f;
        for (int i = 0; i < 16; i++) mx = fmaxf(mx, sz[r][g * 16 + i]);
        float s = 0.f;
        for (int i = 0; i < 16; i++) s += expf(sz[r][g * 16 + i] - mx);
        const float inv = 1.f / s;
        float* o = g_g1 + ((size_t)g * B_ + b0 + r) * 16;
        for (int i = 0; i < 16; i++) o[i] = expf(sz[r][g * 16 + i] - mx) * inv;
    }
}

// ---------------------------------------------------------------------------
// Launch
// ---------------------------------------------------------------------------
extern "C" void kernel_launch(void* const* d_in, const int* in_sizes, int n_in,
                              void* d_out, int out_size) {
    (void)in_sizes; (void)n_in; (void)out_size;
    const float* x    = (const float*)d_in[0];
    const float* ews0 = (const float*)d_in[1];
    const float* ebs0 = (const float*)d_in[2];
    const float* ews1 = (const float*)d_in[3];
    const float* ebs1 = (const float*)d_in[4];
    const float* gws  = (const float*)d_in[5];
    const float* gbs  = (const float*)d_in[6];
    const float* ew0  = (const float*)d_in[7];
    const float* eb0  = (const float*)d_in[8];
    const float* gw0  = (const float*)d_in[9];
    const float* gb0  = (const float*)d_in[10];
    const float* ew1  = (const float*)d_in[11];
    const float* eb1  = (const float*)d_in[12];
    const float* gw1  = (const float*)d_in[13];
    const float* gb1  = (const float*)d_in[14];

    cudaFuncSetAttribute(fgemmS<D_>, cudaFuncAttributeMaxDynamicSharedMemorySize, SMEM_S);
    cudaFuncSetAttribute(fgemmS<U_>, cudaFuncAttributeMaxDynamicSharedMemorySize, SMEM_S);
    cudaFuncSetAttribute(fgemmB0, cudaFuncAttributeMaxDynamicSharedMemorySize, SMEM_B0);
    cudaFuncSetAttribute(fgemmB1, cudaFuncAttributeMaxDynamicSharedMemorySize, SMEM_B1);

    __nv_bfloat16 *xhi, *xlo, *bt0h, *bt0l, *bt1h, *bt1l, *a1h, *a1l;
    cudaGetSymbolAddress((void**)&xhi,  g_xhi);
    cudaGetSymbolAddress((void**)&xlo,  g_xlo);
    cudaGetSymbolAddress((void**)&bt0h, g_bt0h);
    cudaGetSymbolAddress((void**)&bt0l, g_bt0l);
    cudaGetSymbolAddress((void**)&bt1h, g_bt1h);
    cudaGetSymbolAddress((void**)&bt1l, g_bt1l);
    cudaGetSymbolAddress((void**)&a1h,  g_a1h);
    cudaGetSymbolAddress((void**)&a1l,  g_a1l);

    // conversions
    convX<<<(B_ * D_ / 4) / 256, 256>>>(x, xhi, xlo);
    ConvBArgs cb0;
    for (int t = 0; t < 4; t++) cb0.src[t] = ew0 + (size_t)t * D_ * UE;
    cb0.src[4] = ews0; cb0.hi = bt0h; cb0.lo = bt0l; cb0.K = D_;
    convB<<<dim3(NTOT / 32, D_ / 32, 5), dim3(32, 8)>>>(cb0);
    ConvBArgs cb1;
    for (int t = 0; t < 4; t++) cb1.src[t] = ew1 + (size_t)t * U_ * UE;
    cb1.src[4] = ews1; cb1.hi = bt1h; cb1.lo = bt1l; cb1.K = U_;
    convB<<<dim3(NTOT / 32, U_ / 32, 5), dim3(32, 8)>>>(cb1);

    // level 0
    gates0<<<B_ / 16, 256>>>(x, gw0, gb0, gws, gbs);
    fgemmS<D_><<<2048, 256, SMEM_S>>>(xhi, xlo,
        bt0h + (size_t)4 * NTOT * D_, bt0l + (size_t)4 * NTOT * D_, ebs0);
    FGArgs a0;
    for (int t = 0; t < 4; t++) {
        a0.Bh[t] = bt0h + (size_t)t * NTOT * D_;
        a0.Bl[t] = bt0l + (size_t)t * NTOT * D_;
        a0.bias[t] = eb0 + (size_t)t * UE;
    }
    fgemmB0<<<2048, 256, SMEM_B0>>>(a0);

    // level 1
    gates1<<<B_ / 16, 256>>>(gw1, gb1);
    fgemmS<U_><<<2048, 256, SMEM_S>>>(
        a1h + (size_t)4 * B_ * U_, a1l + (size_t)4 * B_ * U_,
        bt1h + (size_t)4 * NTOT * U_, bt1l + (size_t)4 * NTOT * U_, ebs1);
    FGArgs a1;
    for (int t = 0; t < 4; t++) {
        a1.Bh[t] = bt1h + (size_t)t * NTOT * U_;
        a1.Bl[t] = bt1l + (size_t)t * NTOT * U_;
        a1.bias[t] = eb1 + (size_t)t * UE;
    }
    fgemmB1<<<2048, 256, SMEM_B1>>>(a1, (float*)d_out);
}

// round 13
// speedup vs baseline: 3.5581x; 1.3736x over previous
#include <cuda_runtime.h>
#include <cuda_fp16.h>
#include <cstdint>

#define T_  4
#define B_  8192
#define D_  1024
#define U_  512
#define UE  4096
#define NTOT 4096

// ---------------------------------------------------------------------------
// Device scratch
// ---------------------------------------------------------------------------
__device__ float g_Hs[(size_t)B_ * UE];            // shared-expert outputs (reused per level)
__device__ __half g_xhi[(size_t)B_ * D_];
__device__ __half g_xlo[(size_t)B_ * D_];
__device__ __half g_bt0h[5ull * NTOT * D_];        // level-0 B^T (N-major, single fp16 digit)
__device__ __half g_bt1h[5ull * NTOT * U_];
__device__ __half g_a1h[5ull * B_ * U_];           // level-1 A (4 tasks + share), hi/lo
__device__ __half g_a1l[5ull * B_ * U_];
__device__ float g_g0[(size_t)T_ * B_ * 16];
__device__ float g_gs[(size_t)B_ * 40];
__device__ float g_task0[(size_t)T_ * B_ * U_];    // fp32 (gates1 input)
__device__ float g_g1[(size_t)T_ * B_ * 16];

// ---------------------------------------------------------------------------
// PTX helpers (baseline sm_80+ only)
// ---------------------------------------------------------------------------
__device__ __forceinline__ uint32_t smem_u32(const void* p) {
    uint32_t a;
    asm("{ .reg .u64 t; cvta.to.shared.u64 t, %1; cvt.u32.u64 %0, t; }" : "=r"(a) : "l"(p));
    return a;
}
__device__ __forceinline__ void cp16(uint32_t dst, const void* src) {
    asm volatile("cp.async.cg.shared.global [%0], [%1], 16;" :: "r"(dst), "l"(src));
}
__device__ __forceinline__ void ldsm4(uint32_t* r, uint32_t addr) {
    asm volatile("ldmatrix.sync.aligned.m8n8.x4.shared.b16 {%0,%1,%2,%3}, [%4];"
        : "=r"(r[0]), "=r"(r[1]), "=r"(r[2]), "=r"(r[3]) : "r"(addr));
}
__device__ __forceinline__ void mma16816(float* c, const uint32_t* a, uint32_t b0, uint32_t b1) {
    asm volatile("mma.sync.aligned.m16n8k16.row.col.f32.f16.f16.f32 "
        "{%0,%1,%2,%3}, {%4,%5,%6,%7}, {%8,%9}, {%0,%1,%2,%3};"
        : "+f"(c[0]), "+f"(c[1]), "+f"(c[2]), "+f"(c[3])
        : "r"(a[0]), "r"(a[1]), "r"(a[2]), "r"(a[3]), "r"(b0), "r"(b1));
}
__device__ __forceinline__ float red4(float p) {
    p += __shfl_xor_sync(0xffffffffu, p, 1);
    p += __shfl_xor_sync(0xffffffffu, p, 2);
    return p;
}
__device__ __forceinline__ void store_a1(__half* h, __half* l, size_t off, float4 v) {
    __half h0 = __float2half_rn(v.x), h1 = __float2half_rn(v.y);
    __half h2 = __float2half_rn(v.z), h3 = __float2half_rn(v.w);
    *(__half2*)&h[off]     = __half2(h0, h1);
    *(__half2*)&h[off + 2] = __half2(h2, h3);
    *(__half2*)&l[off] = __half2(
        __float2half_rn(v.x - __half2float(h0)),
        __float2half_rn(v.y - __half2float(h1)));
    *(__half2*)&l[off + 2] = __half2(
        __float2half_rn(v.z - __half2float(h2)),
        __float2half_rn(v.w - __half2float(h3)));
}

// ---------------------------------------------------------------------------
// Conversions (fp32 -> fp16; A hi/lo split, B single digit transposed N-major)
// ---------------------------------------------------------------------------
__global__ void convX(const float* __restrict__ x, __half* __restrict__ hi,
                      __half* __restrict__ lo) {
    size_t i = (size_t)blockIdx.x * blockDim.x + threadIdx.x;
    float4 v = ((const float4*)x)[i];
    store_a1(hi, lo, 4 * i, v);
}

struct ConvBArgs { const float* src[5]; __half* hi; int K; };

__global__ void convB(ConvBArgs a) {
    __shared__ float s[32][33];
    const int z = blockIdx.z;
    const float* __restrict__ src = a.src[z];
    const int n0 = blockIdx.x * 32, k0 = blockIdx.y * 32;
    const int tx = threadIdx.x, ty = threadIdx.y;
#pragma unroll
    for (int i = 0; i < 4; i++)
        s[ty + i * 8][tx] = src[(size_t)(k0 + ty + i * 8) * UE + n0 + tx];
    __syncthreads();
    __half* oh = a.hi + (size_t)z * NTOT * a.K;
#pragma unroll
    for (int i = 0; i < 4; i++) {
        const int n = n0 + ty + i * 8, k = k0 + tx;
        oh[(size_t)n * a.K + k] = __float2half_rn(s[tx][ty + i * 8]);
    }
}

// ---------------------------------------------------------------------------
// GEMM machinery: 128x128 tile, K-step 32, 3-stage cp.async (R8-proven
// schedule), 8 warps, fp16 2-product (Ahi/Alo x Bhi).
// ---------------------------------------------------------------------------
#define MAT_BYTES 8192
#define STAGE_BYTES (3 * MAT_BYTES)         // 24 KB: Ahi, Alo, Bhi
#define SMEM_S  (3 * STAGE_BYTES)           // 72 KB (share kernel)
#define SM_STK  (3 * STAGE_BYTES)           // staging float[128][16]
#define SM_SSH  (SM_STK + 8192)
#define SMEM_B0 (SM_SSH + 8192)             // 88 KB
#define SMEM_B1 (SM_STK + 8192)             // 80 KB

template<int KK>
__device__ __forceinline__ void kloop(const __half* __restrict__ A_h,
                                      const __half* __restrict__ A_l,
                                      const __half* __restrict__ B_h,
                                      uint32_t sb, int rlo, int ch, int dsw,
                                      const uint32_t (&aoff)[2][2],
                                      const uint32_t (&boff)[4][2],
                                      float (&acc)[2][8][4]) {
    constexpr int nk = KK / 32;
    const __half* srcs[3] = { A_h, A_l, B_h };
    auto load_stage = [&](int buf, int kc) {
        const uint32_t base = sb + (uint32_t)buf * STAGE_BYTES;
#pragma unroll
        for (int i = 0; i < 6; i++) {
            const int mat = i >> 1;
            const int r   = ((i & 1) << 6) + rlo;
            cp16(base + mat * MAT_BYTES + r * 64 + dsw,
                 srcs[mat] + (size_t)r * KK + kc + ch * 8);
        }
        asm volatile("cp.async.commit_group;" ::: "memory");
    };
    load_stage(0, 0);
    load_stage(1, 32);
    int cb = 0;
    for (int c = 0; c < nk; c++) {
        if (c + 1 < nk) asm volatile("cp.async.wait_group 1;" ::: "memory");
        else            asm volatile("cp.async.wait_group 0;" ::: "memory");
        __syncthreads();
        if (c + 2 < nk) {
            int nb = cb + 2; if (nb >= 3) nb -= 3;
            load_stage(nb, (c + 2) * 32);
        }
        const uint32_t st = sb + (uint32_t)cb * STAGE_BYTES;
        if (++cb == 3) cb = 0;
#pragma unroll
        for (int ks = 0; ks < 2; ks++) {
            uint32_t ahi[2][4], alo[2][4];
#pragma unroll
            for (int i = 0; i < 2; i++) {
                ldsm4(ahi[i], st + aoff[i][ks]);
                ldsm4(alo[i], st + MAT_BYTES + aoff[i][ks]);
            }
            uint32_t bf[4][4];
#pragma unroll
            for (int j = 0; j < 4; j++) ldsm4(bf[j], st + 2 * MAT_BYTES + boff[j][ks]);
#pragma unroll
            for (int i = 0; i < 2; i++)
#pragma unroll
                for (int j = 0; j < 4; j++) {
                    mma16816(acc[i][2 * j],     ahi[i], bf[j][0], bf[j][2]);
                    mma16816(acc[i][2 * j + 1], ahi[i], bf[j][1], bf[j][3]);
                    mma16816(acc[i][2 * j],     alo[i], bf[j][0], bf[j][2]);
                    mma16816(acc[i][2 * j + 1], alo[i], bf[j][1], bf[j][3]);
                }
        }
    }
}

#define GEOM() \
    const int id = blockIdx.x; \
    const int nt = (id >> 4) & 31; \
    const int mt = (id & 15) + ((id >> 9) << 4); \
    const int n0 = nt << 7, m0 = mt << 7; \
    const int u0 = nt << 4; (void)u0; \
    const int tid = threadIdx.x; \
    const int lane = tid & 31; \
    const int w = tid >> 5, wm = w & 3, wn = w >> 2, hb = lane >> 4; \
    const int rlo = tid >> 2, ch = tid & 3; \
    const int dsw = ((ch ^ ((rlo >> 1) & 3)) << 4); \
    uint32_t aoff[2][2], boff[4][2]; \
    _Pragma("unroll") for (int i = 0; i < 2; i++) { \
        const int rA = 32 * wm + 16 * i + (lane & 15); \
        const int csw = (rA >> 1) & 3; \
        _Pragma("unroll") for (int ks = 0; ks < 2; ks++) \
            aoff[i][ks] = (uint32_t)(rA * 64 + (((2 * ks + hb) ^ csw) << 4)); \
    } \
    _Pragma("unroll") for (int j = 0; j < 4; j++) { \
        const int rB = 64 * wn + 16 * j + (((lane >> 3) & 1) << 3) + (lane & 7); \
        const int csw = (rB >> 1) & 3; \
        _Pragma("unroll") for (int ks = 0; ks < 2; ks++) \
            boff[j][ks] = (uint32_t)(rB * 64 + (((2 * ks + hb) ^ csw) << 4)); \
    }

#define ZERO_ACC() \
    float acc[2][8][4]; \
    _Pragma("unroll") for (int i = 0; i < 2; i++) \
        _Pragma("unroll") for (int j = 0; j < 8; j++) \
            _Pragma("unroll") for (int q = 0; q < 4; q++) acc[i][j][q] = 0.f;

// ---------------------------------------------------------------------------
// Share-expert GEMM: Hs = relu(A @ B + bias), plain tile writeback.
// ---------------------------------------------------------------------------
template<int KK>
__global__ __launch_bounds__(256, 2) void fgemmS(const __half* __restrict__ Ah,
                                                 const __half* __restrict__ Al,
                                                 const __half* __restrict__ Bh,
                                                 const float* __restrict__ bias) {
    extern __shared__ __align__(128) char smem[];
    const uint32_t sb = smem_u32(smem);
    GEOM();
    ZERO_ACC();
    kloop<KK>(Ah + (size_t)m0 * KK, Al + (size_t)m0 * KK, Bh + (size_t)n0 * KK,
              sb, rlo, ch, dsw, aoff, boff, acc);
    const int e2 = 2 * (lane & 3);
#pragma unroll
    for (int i = 0; i < 2; i++) {
        const int mr = m0 + 32 * wm + 16 * i + (lane >> 2);
#pragma unroll
        for (int j = 0; j < 8; j++) {
            const int nc = n0 + 64 * wn + 8 * j + e2;
            const float b0v = bias[nc], b1v = bias[nc + 1];
            float2 o0, o1;
            o0.x = fmaxf(acc[i][j][0] + b0v, 0.f);
            o0.y = fmaxf(acc[i][j][1] + b1v, 0.f);
            o1.x = fmaxf(acc[i][j][2] + b0v, 0.f);
            o1.y = fmaxf(acc[i][j][3] + b1v, 0.f);
            *(float2*)(g_Hs + (size_t)mr * UE + nc)       = o0;
            *(float2*)(g_Hs + (size_t)(mr + 8) * UE + nc) = o1;
        }
    }
}

struct FGArgs {
    const __half* Bh[4];
    const float* bias[4];
};

// ---------------------------------------------------------------------------
// Level-0 fused task GEMM: loops t=0..3; epilogue combines gates + es (gmem),
// writes task0 fp32 + a1 fp16 (tasks and share).
// ---------------------------------------------------------------------------
__global__ __launch_bounds__(256, 2) void fgemmB0(FGArgs args) {
    extern __shared__ __align__(128) char smem[];
    const uint32_t sb = smem_u32(smem);
    float* stk = (float*)(smem + SM_STK);
    float* ssh = (float*)(smem + SM_SSH);
    GEOM();
    for (int idx = tid; idx < 2048; idx += 256) ssh[idx] = 0.f;

    const __half* Ah = g_xhi + (size_t)m0 * D_;
    const __half* Al = g_xlo + (size_t)m0 * D_;
    const int e2 = 2 * (lane & 3);

#pragma unroll 1
    for (int t = 0; t < 4; t++) {
        ZERO_ACC();
        kloop<D_>(Ah, Al, args.Bh[t] + (size_t)n0 * D_,
                  sb, rlo, ch, dsw, aoff, boff, acc);

        const float* __restrict__ bias = args.bias[t];
#pragma unroll
        for (int i = 0; i < 2; i++) {
            const int r0 = 32 * wm + 16 * i + (lane >> 2), r1 = r0 + 8;
            const float2 ga0 = *(const float2*)&g_g0[((size_t)t * B_ + m0 + r0) * 16 + e2];
            const float2 gb0 = *(const float2*)&g_g0[((size_t)t * B_ + m0 + r0) * 16 + 8 + e2];
            const float2 ga1 = *(const float2*)&g_g0[((size_t)t * B_ + m0 + r1) * 16 + e2];
            const float2 gb1 = *(const float2*)&g_g0[((size_t)t * B_ + m0 + r1) * 16 + 8 + e2];
            const float2 gt0 = *(const float2*)&g_gs[(size_t)(m0 + r0) * 40 + t * 8 + e2];
            const float2 gt1 = *(const float2*)&g_gs[(size_t)(m0 + r1) * 40 + t * 8 + e2];
            float2 gq0 = {0.f, 0.f}, gq1 = {0.f, 0.f};
            if (t == 3) {
                gq0 = *(const float2*)&g_gs[(size_t)(m0 + r0) * 40 + 32 + e2];
                gq1 = *(const float2*)&g_gs[(size_t)(m0 + r1) * 40 + 32 + e2];
            }
#pragma unroll
            for (int j = 0; j < 8; j++) {
                const int ncl = 64 * wn + 8 * j + e2;
                const float b0v = bias[n0 + ncl], b1v = bias[n0 + ncl + 1];
                const float v00 = fmaxf(acc[i][j][0] + b0v, 0.f);
                const float v01 = fmaxf(acc[i][j][1] + b1v, 0.f);
                const float v10 = fmaxf(acc[i][j][2] + b0v, 0.f);
                const float v11 = fmaxf(acc[i][j][3] + b1v, 0.f);
                const float2 es0 = *(const float2*)&g_Hs[(size_t)(m0 + r0) * UE + n0 + ncl];
                const float2 es1 = *(const float2*)&g_Hs[(size_t)(m0 + r1) * UE + n0 + ncl];
                float pt0 = red4(v00 * ga0.x + v01 * ga0.y + es0.x * gb0.x + es0.y * gb0.y);
                float pt1 = red4(v10 * ga1.x + v11 * ga1.y + es1.x * gb1.x + es1.y * gb1.y);
                float ps0 = v00 * gt0.x + v01 * gt0.y;
                float ps1 = v10 * gt1.x + v11 * gt1.y;
                if (t == 3) {
                    ps0 += es0.x * gq0.x + es0.y * gq0.y;
                    ps1 += es1.x * gq1.x + es1.y * gq1.y;
                }
                ps0 = red4(ps0); ps1 = red4(ps1);
                if ((lane & 3) == 0) {
                    const int u = 8 * wn + j;
                    stk[r0 * 16 + u] = pt0;
                    stk[r1 * 16 + u] = pt1;
                    ssh[r0 * 16 + u] += ps0;
                    ssh[r1 * 16 + u] += ps1;
                }
            }
        }
        __syncthreads();
        for (int idx = tid; idx < 512; idx += 256) {
            const int r = idx >> 2, c4 = idx & 3;
            float4 tv = *(float4*)&stk[r * 16 + 4 * c4];
            const size_t off = ((size_t)t * B_ + m0 + r) * U_ + u0 + 4 * c4;
            *(float4*)&g_task0[off] = tv;
            store_a1(g_a1h, g_a1l, off, tv);
        }
        __syncthreads();
    }

    for (int idx = tid; idx < 512; idx += 256) {
        const int r = idx >> 2, c4 = idx & 3;
        float4 sv = *(float4*)&ssh[r * 16 + 4 * c4];
        store_a1(g_a1h, g_a1l, ((size_t)4 * B_ + m0 + r) * U_ + u0 + 4 * c4, sv);
    }
}

// ---------------------------------------------------------------------------
// Level-1 fused task GEMM: writes final out directly.
// ---------------------------------------------------------------------------
__global__ __launch_bounds__(256, 2) void fgemmB1(FGArgs args, float* __restrict__ out) {
    extern __shared__ __align__(128) char smem[];
    const uint32_t sb = smem_u32(smem);
    float* stk = (float*)(smem + SM_STK);
    GEOM();
    const int e2 = 2 * (lane & 3);

#pragma unroll 1
    for (int t = 0; t < 4; t++) {
        ZERO_ACC();
        kloop<U_>(g_a1h + ((size_t)t * B_ + m0) * U_, g_a1l + ((size_t)t * B_ + m0) * U_,
                  args.Bh[t] + (size_t)n0 * U_,
                  sb, rlo, ch, dsw, aoff, boff, acc);

        const float* __restrict__ bias = args.bias[t];
#pragma unroll
        for (int i = 0; i < 2; i++) {
            const int r0 = 32 * wm + 16 * i + (lane >> 2), r1 = r0 + 8;
            const float2 ga0 = *(const float2*)&g_g1[((size_t)t * B_ + m0 + r0) * 16 + e2];
            const float2 gb0 = *(const float2*)&g_g1[((size_t)t * B_ + m0 + r0) * 16 + 8 + e2];
            const float2 ga1 = *(const float2*)&g_g1[((size_t)t * B_ + m0 + r1) * 16 + e2];
            const float2 gb1 = *(const float2*)&g_g1[((size_t)t * B_ + m0 + r1) * 16 + 8 + e2];
#pragma unroll
            for (int j = 0; j < 8; j++) {
                const int ncl = 64 * wn + 8 * j + e2;
                const float b0v = bias[n0 + ncl], b1v = bias[n0 + ncl + 1];
                const float v00 = fmaxf(acc[i][j][0] + b0v, 0.f);
                const float v01 = fmaxf(acc[i][j][1] + b1v, 0.f);
                const float v10 = fmaxf(acc[i][j][2] + b0v, 0.f);
                const float v11 = fmaxf(acc[i][j][3] + b1v, 0.f);
                const float2 es0 = *(const float2*)&g_Hs[(size_t)(m0 + r0) * UE + n0 + ncl];
                const float2 es1 = *(const float2*)&g_Hs[(size_t)(m0 + r1) * UE + n0 + ncl];
                float pt0 = red4(v00 * ga0.x + v01 * ga0.y + es0.x * gb0.x + es0.y * gb0.y);
                float pt1 = red4(v10 * ga1.x + v11 * ga1.y + es1.x * gb1.x + es1.y * gb1.y);
                if ((lane & 3) == 0) {
                    const int u = 8 * wn + j;
                    stk[r0 * 16 + u] = pt0;
                    stk[r1 * 16 + u] = pt1;
                }
            }
        }
        __syncthreads();
        for (int idx = tid; idx < 512; idx += 256) {
            const int r = idx >> 2, c4 = idx & 3;
            float4 tv = *(float4*)&stk[r * 16 + 4 * c4];
            *(float4*)&out[((size_t)t * B_ + m0 + r) * U_ + u0 + 4 * c4] = tv;
        }
        __syncthreads();
    }
}

// ---------------------------------------------------------------------------
// gates0 / gates1 (R8 fast versions, unchanged)
// ---------------------------------------------------------------------------
__global__ __launch_bounds__(256) void gates0(const float* __restrict__ x,
                                              const float* __restrict__ gw0,
                                              const float* __restrict__ gb0,
                                              const float* __restrict__ gws,
                                              const float* __restrict__ gbs) {
    const int b0 = blockIdx.x * 16;
    const int tid = threadIdx.x;
    __shared__ float sx[16][128];
    __shared__ float sz[16][104];

    const bool active = tid < 208;
    const int rh = (tid >= 104) ? 1 : 0;
    const int c  = active ? (tid - rh * 104) : 0;

    const float* Wp; int wstride;
    if (c < 64) { Wp = gw0 + (size_t)(c >> 4) * D_ * 16 + (c & 15); wstride = 16; }
    else        { Wp = gws + (c - 64);                              wstride = 40; }

    float acc[8];
#pragma unroll
    for (int r = 0; r < 8; r++) acc[r] = 0.f;

    for (int kc = 0; kc < D_ / 128; kc++) {
        __syncthreads();
#pragma unroll
        for (int p = 0; p < 2; p++) {
            const int idx = tid + p * 256;
            const int row = idx >> 5, c4 = idx & 31;
            *(float4*)&sx[row][c4 * 4] =
                *(const float4*)(x + (size_t)(b0 + row) * D_ + kc * 128 + c4 * 4);
        }
        __syncthreads();
        if (active) {
            const float* wp = Wp + (size_t)kc * 128 * wstride;
#pragma unroll 4
            for (int k = 0; k < 128; k += 4) {
                const float w0 = wp[(k + 0) * wstride];
                const float w1 = wp[(k + 1) * wstride];
                const float w2 = wp[(k + 2) * wstride];
                const float w3 = wp[(k + 3) * wstride];
#pragma unroll
                for (int r = 0; r < 8; r++) {
                    float4 xv = *(const float4*)&sx[rh * 8 + r][k];
                    acc[r] += xv.x * w0 + xv.y * w1 + xv.z * w2 + xv.w * w3;
                }
            }
        }
    }
    if (active) {
        const float bb = (c < 64) ? gb0[c] : gbs[c - 64];
#pragma unroll
        for (int r = 0; r < 8; r++) sz[rh * 8 + r][c] = acc[r] + bb;
    }
    __syncthreads();

    if (tid < 80) {
        const int r = tid & 15, g = tid >> 4;
        const int base = (g < 4) ? g * 16 : 64;
        const int len  = (g < 4) ? 16 : 40;
        float mx = -1e30f;
        for (int i = 0; i < len; i++) mx = fmaxf(mx, sz[r][base + i]);
        float s = 0.f;
        for (int i = 0; i < len; i++) s += expf(sz[r][base + i] - mx);
        const float inv = 1.f / s;
        if (g < 4) {
            float* o = g_g0 + ((size_t)g * B_ + b0 + r) * 16;
            for (int i = 0; i < 16; i++) o[i] = expf(sz[r][base + i] - mx) * inv;
        } else {
            float* o = g_gs + (size_t)(b0 + r) * 40;
            for (int i = 0; i < 40; i++) o[i] = expf(sz[r][base + i] - mx) * inv;
        }
    }
}

__global__ __launch_bounds__(256) void gates1(const float* __restrict__ gw1,
                                              const float* __restrict__ gb1) {
    const int b0 = blockIdx.x * 16;
    const int tid = threadIdx.x;
    __shared__ float s1[4][16][128];
    __shared__ float sz[16][64];

    const bool active = tid < 128;
    const int rh = (tid >> 6) & 1;
    const int c  = tid & 63;
    const int tt = c >> 4;
    const float* Wp = gw1 + (size_t)tt * U_ * 16 + (c & 15);

    float acc[8];
#pragma unroll
    for (int r = 0; r < 8; r++) acc[r] = 0.f;

    for (int kc = 0; kc < U_ / 128; kc++) {
        __syncthreads();
#pragma unroll
        for (int p = 0; p < 8; p++) {
            const int idx = tid + p * 256;
            const int tz = idx >> 9, row = (idx >> 5) & 15, c4 = idx & 31;
            *(float4*)&s1[tz][row][c4 * 4] =
                *(const float4*)(g_task0 + ((size_t)tz * B_ + b0 + row) * U_ + kc * 128 + c4 * 4);
        }
        __syncthreads();
        if (active) {
            const float* wp = Wp + (size_t)kc * 128 * 16;
#pragma unroll 4
            for (int k = 0; k < 128; k += 4) {
                const float w0 = wp[(k + 0) * 16];
                const float w1 = wp[(k + 1) * 16];
                const float w2 = wp[(k + 2) * 16];
                const float w3 = wp[(k + 3) * 16];
#pragma unroll
                for (int r = 0; r < 8; r++) {
                    float4 xv = *(const float4*)&s1[tt][rh * 8 + r][k];
                    acc[r] += xv.x * w0 + xv.y * w1 + xv.z * w2 + xv.w * w3;
                }
            }
        }
    }
    if (active) {
        const float bb = gb1[c];
#pragma unroll
        for (int r = 0; r < 8; r++) sz[rh * 8 + r][c] = acc[r] + bb;
    }
    __syncthreads();

    if (tid < 64) {
        const int r = tid & 15, g = tid >> 4;
        float mx = -1e30f;
        for (int i = 0; i < 16; i++) mx = fmaxf(mx, sz[r][g * 16 + i]);
        float s = 0.f;
        for (int i = 0; i < 16; i++) s += expf(sz[r][g * 16 + i] - mx);
        const float inv = 1.f / s;
        float* o = g_g1 + ((size_t)g * B_ + b0 + r) * 16;
        for (int i = 0; i < 16; i++) o[i] = expf(sz[r][g * 16 + i] - mx) * inv;
    }
}

// ---------------------------------------------------------------------------
// Launch
// ---------------------------------------------------------------------------
extern "C" void kernel_launch(void* const* d_in, const int* in_sizes, int n_in,
                              void* d_out, int out_size) {
    (void)in_sizes; (void)n_in; (void)out_size;
    const float* x    = (const float*)d_in[0];
    const float* ews0 = (const float*)d_in[1];
    const float* ebs0 = (const float*)d_in[2];
    const float* ews1 = (const float*)d_in[3];
    const float* ebs1 = (const float*)d_in[4];
    const float* gws  = (const float*)d_in[5];
    const float* gbs  = (const float*)d_in[6];
    const float* ew0  = (const float*)d_in[7];
    const float* eb0  = (const float*)d_in[8];
    const float* gw0  = (const float*)d_in[9];
    const float* gb0  = (const float*)d_in[10];
    const float* ew1  = (const float*)d_in[11];
    const float* eb1  = (const float*)d_in[12];
    const float* gw1  = (const float*)d_in[13];
    const float* gb1  = (const float*)d_in[14];

    cudaFuncSetAttribute(fgemmS<D_>, cudaFuncAttributeMaxDynamicSharedMemorySize, SMEM_S);
    cudaFuncSetAttribute(fgemmS<U_>, cudaFuncAttributeMaxDynamicSharedMemorySize, SMEM_S);
    cudaFuncSetAttribute(fgemmB0, cudaFuncAttributeMaxDynamicSharedMemorySize, SMEM_B0);
    cudaFuncSetAttribute(fgemmB1, cudaFuncAttributeMaxDynamicSharedMemorySize, SMEM_B1);

    __half *xhi, *xlo, *bt0h, *bt1h, *a1h, *a1l;
    cudaGetSymbolAddress((void**)&xhi,  g_xhi);
    cudaGetSymbolAddress((void**)&xlo,  g_xlo);
    cudaGetSymbolAddress((void**)&bt0h, g_bt0h);
    cudaGetSymbolAddress((void**)&bt1h, g_bt1h);
    cudaGetSymbolAddress((void**)&a1h,  g_a1h);
    cudaGetSymbolAddress((void**)&a1l,  g_a1l);

    // conversions
    convX<<<(B_ * D_ / 4) / 256, 256>>>(x, xhi, xlo);
    ConvBArgs cb0;
    for (int t = 0; t < 4; t++) cb0.src[t] = ew0 + (size_t)t * D_ * UE;
    cb0.src[4] = ews0; cb0.hi = bt0h; cb0.K = D_;
    convB<<<dim3(NTOT / 32, D_ / 32, 5), dim3(32, 8)>>>(cb0);
    ConvBArgs cb1;
    for (int t = 0; t < 4; t++) cb1.src[t] = ew1 + (size_t)t * U_ * UE;
    cb1.src[4] = ews1; cb1.hi = bt1h; cb1.K = U_;
    convB<<<dim3(NTOT / 32, U_ / 32, 5), dim3(32, 8)>>>(cb1);

    // level 0
    gates0<<<B_ / 16, 256>>>(x, gw0, gb0, gws, gbs);
    fgemmS<D_><<<2048, 256, SMEM_S>>>(xhi, xlo,
        bt0h + (size_t)4 * NTOT * D_, ebs0);
    FGArgs a0;
    for (int t = 0; t < 4; t++) {
        a0.Bh[t] = bt0h + (size_t)t * NTOT * D_;
        a0.bias[t] = eb0 + (size_t)t * UE;
    }
    fgemmB0<<<2048, 256, SMEM_B0>>>(a0);

    // level 1
    gates1<<<B_ / 16, 256>>>(gw1, gb1);
    fgemmS<U_><<<2048, 256, SMEM_S>>>(
        a1h + (size_t)4 * B_ * U_, a1l + (size_t)4 * B_ * U_,
        bt1h + (size_t)4 * NTOT * U_, ebs1);
    FGArgs a1;
    for (int t = 0; t < 4; t++) {
        a1.Bh[t] = bt1h + (size_t)t * NTOT * U_;
        a1.bias[t] = eb1 + (size_t)t * UE;
    }
    fgemmB1<<<2048, 256, SMEM_B1>>>(a1, (float*)d_out);
}

// round 14
// speedup vs baseline: 5.5259x; 1.5530x over previous
#include <cuda_runtime.h>
#include <cuda_fp16.h>
#include <cstdint>

#define T_  4
#define B_  8192
#define D_  1024
#define U_  512
#define UE  4096
#define NTOT 4096

// ---------------------------------------------------------------------------
// Device scratch
// ---------------------------------------------------------------------------
__device__ float g_Hs[(size_t)B_ * UE];            // shared-expert outputs (reused per level)
__device__ __half g_xh[(size_t)B_ * D_];           // x in fp16 (single digit)
__device__ __half g_bt0h[5ull * NTOT * D_];        // level-0 B^T (N-major, fp16)
__device__ __half g_bt1h[5ull * NTOT * U_];
__device__ __half g_a1h[5ull * B_ * U_];           // level-1 A (4 tasks + share), fp16
__device__ float g_g0[(size_t)T_ * B_ * 16];
__device__ float g_gs[(size_t)B_ * 40];
__device__ float g_task0[(size_t)T_ * B_ * U_];    // fp32 (gates1 input)
__device__ float g_g1[(size_t)T_ * B_ * 16];

// ---------------------------------------------------------------------------
// PTX helpers (baseline sm_80+ only)
// ---------------------------------------------------------------------------
__device__ __forceinline__ uint32_t smem_u32(const void* p) {
    uint32_t a;
    asm("{ .reg .u64 t; cvta.to.shared.u64 t, %1; cvt.u32.u64 %0, t; }" : "=r"(a) : "l"(p));
    return a;
}
__device__ __forceinline__ void cp16(uint32_t dst, const void* src) {
    asm volatile("cp.async.cg.shared.global [%0], [%1], 16;" :: "r"(dst), "l"(src));
}
__device__ __forceinline__ void ldsm4(uint32_t* r, uint32_t addr) {
    asm volatile("ldmatrix.sync.aligned.m8n8.x4.shared.b16 {%0,%1,%2,%3}, [%4];"
        : "=r"(r[0]), "=r"(r[1]), "=r"(r[2]), "=r"(r[3]) : "r"(addr));
}
__device__ __forceinline__ void mma16816(float* c, const uint32_t* a, uint32_t b0, uint32_t b1) {
    asm volatile("mma.sync.aligned.m16n8k16.row.col.f32.f16.f16.f32 "
        "{%0,%1,%2,%3}, {%4,%5,%6,%7}, {%8,%9}, {%0,%1,%2,%3};"
        : "+f"(c[0]), "+f"(c[1]), "+f"(c[2]), "+f"(c[3])
        : "r"(a[0]), "r"(a[1]), "r"(a[2]), "r"(a[3]), "r"(b0), "r"(b1));
}
__device__ __forceinline__ float red4(float p) {
    p += __shfl_xor_sync(0xffffffffu, p, 1);
    p += __shfl_xor_sync(0xffffffffu, p, 2);
    return p;
}
__device__ __forceinline__ void store_h4(__half* h, size_t off, float4 v) {
    *(__half2*)&h[off]     = __half2(__float2half_rn(v.x), __float2half_rn(v.y));
    *(__half2*)&h[off + 2] = __half2(__float2half_rn(v.z), __float2half_rn(v.w));
}

// ---------------------------------------------------------------------------
// Conversions (fp32 -> fp16; B transposed to N-major)
// ---------------------------------------------------------------------------
__global__ void convX(const float* __restrict__ x, __half* __restrict__ hi) {
    size_t i = (size_t)blockIdx.x * blockDim.x + threadIdx.x;
    float4 v = ((const float4*)x)[i];
    store_h4(hi, 4 * i, v);
}

struct ConvBArgs { const float* src[5]; __half* hi; int K; };

__global__ void convB(ConvBArgs a) {
    __shared__ float s[32][33];
    const int z = blockIdx.z;
    const float* __restrict__ src = a.src[z];
    const int n0 = blockIdx.x * 32, k0 = blockIdx.y * 32;
    const int tx = threadIdx.x, ty = threadIdx.y;
#pragma unroll
    for (int i = 0; i < 4; i++)
        s[ty + i * 8][tx] = src[(size_t)(k0 + ty + i * 8) * UE + n0 + tx];
    __syncthreads();
    __half* oh = a.hi + (size_t)z * NTOT * a.K;
#pragma unroll
    for (int i = 0; i < 4; i++) {
        const int n = n0 + ty + i * 8, k = k0 + tx;
        oh[(size_t)n * a.K + k] = __float2half_rn(s[tx][ty + i * 8]);
    }
}

// ---------------------------------------------------------------------------
// GEMM machinery: 128x128 tile, K-step 32, 3-stage cp.async (R8-proven
// schedule), 8 warps, single-product fp16 (Ah x Bh).
// ---------------------------------------------------------------------------
#define MAT_BYTES 8192
#define STAGE_BYTES (2 * MAT_BYTES)         // 16 KB: Ah, Bh
#define SMEM_S  (3 * STAGE_BYTES)           // 48 KB (share kernel)
#define SM_STK  (3 * STAGE_BYTES)           // staging float[128][16]
#define SM_SSH  (SM_STK + 8192)
#define SMEM_B0 (SM_SSH + 8192)             // 64 KB
#define SMEM_B1 (SM_STK + 8192)             // 56 KB

template<int KK>
__device__ __forceinline__ void kloop(const __half* __restrict__ A_h,
                                      const __half* __restrict__ B_h,
                                      uint32_t sb, int rlo, int ch, int dsw,
                                      const uint32_t (&aoff)[2][2],
                                      const uint32_t (&boff)[4][2],
                                      float (&acc)[2][8][4]) {
    constexpr int nk = KK / 32;
    const __half* srcs[2] = { A_h, B_h };
    auto load_stage = [&](int buf, int kc) {
        const uint32_t base = sb + (uint32_t)buf * STAGE_BYTES;
#pragma unroll
        for (int i = 0; i < 4; i++) {
            const int mat = i >> 1;
            const int r   = ((i & 1) << 6) + rlo;
            cp16(base + mat * MAT_BYTES + r * 64 + dsw,
                 srcs[mat] + (size_t)r * KK + kc + ch * 8);
        }
        asm volatile("cp.async.commit_group;" ::: "memory");
    };
    load_stage(0, 0);
    load_stage(1, 32);
    int cb = 0;
    for (int c = 0; c < nk; c++) {
        if (c + 1 < nk) asm volatile("cp.async.wait_group 1;" ::: "memory");
        else            asm volatile("cp.async.wait_group 0;" ::: "memory");
        __syncthreads();
        if (c + 2 < nk) {
            int nb = cb + 2; if (nb >= 3) nb -= 3;
            load_stage(nb, (c + 2) * 32);
        }
        const uint32_t st = sb + (uint32_t)cb * STAGE_BYTES;
        if (++cb == 3) cb = 0;
#pragma unroll
        for (int ks = 0; ks < 2; ks++) {
            uint32_t ah[2][4];
#pragma unroll
            for (int i = 0; i < 2; i++) ldsm4(ah[i], st + aoff[i][ks]);
            uint32_t bf[4][4];
#pragma unroll
            for (int j = 0; j < 4; j++) ldsm4(bf[j], st + MAT_BYTES + boff[j][ks]);
#pragma unroll
            for (int i = 0; i < 2; i++)
#pragma unroll
                for (int j = 0; j < 4; j++) {
                    mma16816(acc[i][2 * j],     ah[i], bf[j][0], bf[j][2]);
                    mma16816(acc[i][2 * j + 1], ah[i], bf[j][1], bf[j][3]);
                }
        }
    }
}

#define GEOM() \
    const int id = blockIdx.x; \
    const int nt = (id >> 4) & 31; \
    const int mt = (id & 15) + ((id >> 9) << 4); \
    const int n0 = nt << 7, m0 = mt << 7; \
    const int u0 = nt << 4; (void)u0; \
    const int tid = threadIdx.x; \
    const int lane = tid & 31; \
    const int w = tid >> 5, wm = w & 3, wn = w >> 2, hb = lane >> 4; \
    const int rlo = tid >> 2, ch = tid & 3; \
    const int dsw = ((ch ^ ((rlo >> 1) & 3)) << 4); \
    uint32_t aoff[2][2], boff[4][2]; \
    _Pragma("unroll") for (int i = 0; i < 2; i++) { \
        const int rA = 32 * wm + 16 * i + (lane & 15); \
        const int csw = (rA >> 1) & 3; \
        _Pragma("unroll") for (int ks = 0; ks < 2; ks++) \
            aoff[i][ks] = (uint32_t)(rA * 64 + (((2 * ks + hb) ^ csw) << 4)); \
    } \
    _Pragma("unroll") for (int j = 0; j < 4; j++) { \
        const int rB = 64 * wn + 16 * j + (((lane >> 3) & 1) << 3) + (lane & 7); \
        const int csw = (rB >> 1) & 3; \
        _Pragma("unroll") for (int ks = 0; ks < 2; ks++) \
            boff[j][ks] = (uint32_t)(rB * 64 + (((2 * ks + hb) ^ csw) << 4)); \
    }

#define ZERO_ACC() \
    float acc[2][8][4]; \
    _Pragma("unroll") for (int i = 0; i < 2; i++) \
        _Pragma("unroll") for (int j = 0; j < 8; j++) \
            _Pragma("unroll") for (int q = 0; q < 4; q++) acc[i][j][q] = 0.f;

// ---------------------------------------------------------------------------
// Share-expert GEMM: Hs = relu(A @ B + bias), plain tile writeback.
// ---------------------------------------------------------------------------
template<int KK>
__global__ __launch_bounds__(256, 2) void fgemmS(const __half* __restrict__ Ah,
                                                 const __half* __restrict__ Bh,
                                                 const float* __restrict__ bias) {
    extern __shared__ __align__(128) char smem[];
    const uint32_t sb = smem_u32(smem);
    GEOM();
    ZERO_ACC();
    kloop<KK>(Ah + (size_t)m0 * KK, Bh + (size_t)n0 * KK,
              sb, rlo, ch, dsw, aoff, boff, acc);
    const int e2 = 2 * (lane & 3);
#pragma unroll
    for (int i = 0; i < 2; i++) {
        const int mr = m0 + 32 * wm + 16 * i + (lane >> 2);
#pragma unroll
        for (int j = 0; j < 8; j++) {
            const int nc = n0 + 64 * wn + 8 * j + e2;
            const float b0v = bias[nc], b1v = bias[nc + 1];
            float2 o0, o1;
            o0.x = fmaxf(acc[i][j][0] + b0v, 0.f);
            o0.y = fmaxf(acc[i][j][1] + b1v, 0.f);
            o1.x = fmaxf(acc[i][j][2] + b0v, 0.f);
            o1.y = fmaxf(acc[i][j][3] + b1v, 0.f);
            *(float2*)(g_Hs + (size_t)mr * UE + nc)       = o0;
            *(float2*)(g_Hs + (size_t)(mr + 8) * UE + nc) = o1;
        }
    }
}

struct FGArgs {
    const __half* Bh[4];
    const float* bias[4];
};

// ---------------------------------------------------------------------------
// Level-0 fused task GEMM: loops t=0..3; epilogue combines gates + es (gmem),
// writes task0 fp32 + a1 fp16 (tasks and share).
// ---------------------------------------------------------------------------
__global__ __launch_bounds__(256, 2) void fgemmB0(FGArgs args) {
    extern __shared__ __align__(128) char smem[];
    const uint32_t sb = smem_u32(smem);
    float* stk = (float*)(smem + SM_STK);
    float* ssh = (float*)(smem + SM_SSH);
    GEOM();
    for (int idx = tid; idx < 2048; idx += 256) ssh[idx] = 0.f;

    const __half* Ah = g_xh + (size_t)m0 * D_;
    const int e2 = 2 * (lane & 3);

#pragma unroll 1
    for (int t = 0; t < 4; t++) {
        ZERO_ACC();
        kloop<D_>(Ah, args.Bh[t] + (size_t)n0 * D_,
                  sb, rlo, ch, dsw, aoff, boff, acc);

        const float* __restrict__ bias = args.bias[t];
#pragma unroll
        for (int i = 0; i < 2; i++) {
            const int r0 = 32 * wm + 16 * i + (lane >> 2), r1 = r0 + 8;
            const float2 ga0 = *(const float2*)&g_g0[((size_t)t * B_ + m0 + r0) * 16 + e2];
            const float2 gb0 = *(const float2*)&g_g0[((size_t)t * B_ + m0 + r0) * 16 + 8 + e2];
            const float2 ga1 = *(const float2*)&g_g0[((size_t)t * B_ + m0 + r1) * 16 + e2];
            const float2 gb1 = *(const float2*)&g_g0[((size_t)t * B_ + m0 + r1) * 16 + 8 + e2];
            const float2 gt0 = *(const float2*)&g_gs[(size_t)(m0 + r0) * 40 + t * 8 + e2];
            const float2 gt1 = *(const float2*)&g_gs[(size_t)(m0 + r1) * 40 + t * 8 + e2];
            float2 gq0 = {0.f, 0.f}, gq1 = {0.f, 0.f};
            if (t == 3) {
                gq0 = *(const float2*)&g_gs[(size_t)(m0 + r0) * 40 + 32 + e2];
                gq1 = *(const float2*)&g_gs[(size_t)(m0 + r1) * 40 + 32 + e2];
            }
#pragma unroll
            for (int j = 0; j < 8; j++) {
                const int ncl = 64 * wn + 8 * j + e2;
                const float b0v = bias[n0 + ncl], b1v = bias[n0 + ncl + 1];
                const float v00 = fmaxf(acc[i][j][0] + b0v, 0.f);
                const float v01 = fmaxf(acc[i][j][1] + b1v, 0.f);
                const float v10 = fmaxf(acc[i][j][2] + b0v, 0.f);
                const float v11 = fmaxf(acc[i][j][3] + b1v, 0.f);
                const float2 es0 = *(const float2*)&g_Hs[(size_t)(m0 + r0) * UE + n0 + ncl];
                const float2 es1 = *(const float2*)&g_Hs[(size_t)(m0 + r1) * UE + n0 + ncl];
                float pt0 = red4(v00 * ga0.x + v01 * ga0.y + es0.x * gb0.x + es0.y * gb0.y);
                float pt1 = red4(v10 * ga1.x + v11 * ga1.y + es1.x * gb1.x + es1.y * gb1.y);
                float ps0 = v00 * gt0.x + v01 * gt0.y;
                float ps1 = v10 * gt1.x + v11 * gt1.y;
                if (t == 3) {
                    ps0 += es0.x * gq0.x + es0.y * gq0.y;
                    ps1 += es1.x * gq1.x + es1.y * gq1.y;
                }
                ps0 = red4(ps0); ps1 = red4(ps1);
                if ((lane & 3) == 0) {
                    const int u = 8 * wn + j;
                    stk[r0 * 16 + u] = pt0;
                    stk[r1 * 16 + u] = pt1;
                    ssh[r0 * 16 + u] += ps0;
                    ssh[r1 * 16 + u] += ps1;
                }
            }
        }
        __syncthreads();
        for (int idx = tid; idx < 512; idx += 256) {
            const int r = idx >> 2, c4 = idx & 3;
            float4 tv = *(float4*)&stk[r * 16 + 4 * c4];
            const size_t off = ((size_t)t * B_ + m0 + r) * U_ + u0 + 4 * c4;
            *(float4*)&g_task0[off] = tv;
            store_h4(g_a1h, off, tv);
        }
        __syncthreads();
    }

    for (int idx = tid; idx < 512; idx += 256) {
        const int r = idx >> 2, c4 = idx & 3;
        float4 sv = *(float4*)&ssh[r * 16 + 4 * c4];
        store_h4(g_a1h, ((size_t)4 * B_ + m0 + r) * U_ + u0 + 4 * c4, sv);
    }
}

// ---------------------------------------------------------------------------
// Level-1 fused task GEMM: writes final out directly.
// ---------------------------------------------------------------------------
__global__ __launch_bounds__(256, 2) void fgemmB1(FGArgs args, float* __restrict__ out) {
    extern __shared__ __align__(128) char smem[];
    const uint32_t sb = smem_u32(smem);
    float* stk = (float*)(smem + SM_STK);
    GEOM();
    const int e2 = 2 * (lane & 3);

#pragma unroll 1
    for (int t = 0; t < 4; t++) {
        ZERO_ACC();
        kloop<U_>(g_a1h + ((size_t)t * B_ + m0) * U_,
                  args.Bh[t] + (size_t)n0 * U_,
                  sb, rlo, ch, dsw, aoff, boff, acc);

        const float* __restrict__ bias = args.bias[t];
#pragma unroll
        for (int i = 0; i < 2; i++) {
            const int r0 = 32 * wm + 16 * i + (lane >> 2), r1 = r0 + 8;
            const float2 ga0 = *(const float2*)&g_g1[((size_t)t * B_ + m0 + r0) * 16 + e2];
            const float2 gb0 = *(const float2*)&g_g1[((size_t)t * B_ + m0 + r0) * 16 + 8 + e2];
            const float2 ga1 = *(const float2*)&g_g1[((size_t)t * B_ + m0 + r1) * 16 + e2];
            const float2 gb1 = *(const float2*)&g_g1[((size_t)t * B_ + m0 + r1) * 16 + 8 + e2];
#pragma unroll
            for (int j = 0; j < 8; j++) {
                const int ncl = 64 * wn + 8 * j + e2;
                const float b0v = bias[n0 + ncl], b1v = bias[n0 + ncl + 1];
                const float v00 = fmaxf(acc[i][j][0] + b0v, 0.f);
                const float v01 = fmaxf(acc[i][j][1] + b1v, 0.f);
                const float v10 = fmaxf(acc[i][j][2] + b0v, 0.f);
                const float v11 = fmaxf(acc[i][j][3] + b1v, 0.f);
                const float2 es0 = *(const float2*)&g_Hs[(size_t)(m0 + r0) * UE + n0 + ncl];
                const float2 es1 = *(const float2*)&g_Hs[(size_t)(m0 + r1) * UE + n0 + ncl];
                float pt0 = red4(v00 * ga0.x + v01 * ga0.y + es0.x * gb0.x + es0.y * gb0.y);
                float pt1 = red4(v10 * ga1.x + v11 * ga1.y + es1.x * gb1.x + es1.y * gb1.y);
                if ((lane & 3) == 0) {
                    const int u = 8 * wn + j;
                    stk[r0 * 16 + u] = pt0;
                    stk[r1 * 16 + u] = pt1;
                }
            }
        }
        __syncthreads();
        for (int idx = tid; idx < 512; idx += 256) {
            const int r = idx >> 2, c4 = idx & 3;
            float4 tv = *(float4*)&stk[r * 16 + 4 * c4];
            *(float4*)&out[((size_t)t * B_ + m0 + r) * U_ + u0 + 4 * c4] = tv;
        }
        __syncthreads();
    }
}

// ---------------------------------------------------------------------------
// gates0 / gates1 (R8 fast versions, unchanged)
// ---------------------------------------------------------------------------
__global__ __launch_bounds__(256) void gates0(const float* __restrict__ x,
                                              const float* __restrict__ gw0,
                                              const float* __restrict__ gb0,
                                              const float* __restrict__ gws,
                                              const float* __restrict__ gbs) {
    const int b0 = blockIdx.x * 16;
    const int tid = threadIdx.x;
    __shared__ float sx[16][128];
    __shared__ float sz[16][104];

    const bool active = tid < 208;
    const int rh = (tid >= 104) ? 1 : 0;
    const int c  = active ? (tid - rh * 104) : 0;

    const float* Wp; int wstride;
    if (c < 64) { Wp = gw0 + (size_t)(c >> 4) * D_ * 16 + (c & 15); wstride = 16; }
    else        { Wp = gws + (c - 64);                              wstride = 40; }

    float acc[8];
#pragma unroll
    for (int r = 0; r < 8; r++) acc[r] = 0.f;

    for (int kc = 0; kc < D_ / 128; kc++) {
        __syncthreads();
#pragma unroll
        for (int p = 0; p < 2; p++) {
            const int idx = tid + p * 256;
            const int row = idx >> 5, c4 = idx & 31;
            *(float4*)&sx[row][c4 * 4] =
                *(const float4*)(x + (size_t)(b0 + row) * D_ + kc * 128 + c4 * 4);
        }
        __syncthreads();
        if (active) {
            const float* wp = Wp + (size_t)kc * 128 * wstride;
#pragma unroll 4
            for (int k = 0; k < 128; k += 4) {
                const float w0 = wp[(k + 0) * wstride];
                const float w1 = wp[(k + 1) * wstride];
                const float w2 = wp[(k + 2) * wstride];
                const float w3 = wp[(k + 3) * wstride];
#pragma unroll
                for (int r = 0; r < 8; r++) {
                    float4 xv = *(const float4*)&sx[rh * 8 + r][k];
                    acc[r] += xv.x * w0 + xv.y * w1 + xv.z * w2 + xv.w * w3;
                }
            }
        }
    }
    if (active) {
        const float bb = (c < 64) ? gb0[c] : gbs[c - 64];
#pragma unroll
        for (int r = 0; r < 8; r++) sz[rh * 8 + r][c] = acc[r] + bb;
    }
    __syncthreads();

    if (tid < 80) {
        const int r = tid & 15, g = tid >> 4;
        const int base = (g < 4) ? g * 16 : 64;
        const int len  = (g < 4) ? 16 : 40;
        float mx = -1e30f;
        for (int i = 0; i < len; i++) mx = fmaxf(mx, sz[r][base + i]);
        float s = 0.f;
        for (int i = 0; i < len; i++) s += expf(sz[r][base + i] - mx);
        const float inv = 1.f / s;
        if (g < 4) {
            float* o = g_g0 + ((size_t)g * B_ + b0 + r) * 16;
            for (int i = 0; i < 16; i++) o[i] = expf(sz[r][base + i] - mx) * inv;
        } else {
            float* o = g_gs + (size_t)(b0 + r) * 40;
            for (int i = 0; i < 40; i++) o[i] = expf(sz[r][base + i] - mx) * inv;
        }
    }
}

__global__ __launch_bounds__(256) void gates1(const float* __restrict__ gw1,
                                              const float* __restrict__ gb1) {
    const int b0 = blockIdx.x * 16;
    const int tid = threadIdx.x;
    __shared__ float s1[4][16][128];
    __shared__ float sz[16][64];

    const bool active = tid < 128;
    const int rh = (tid >> 6) & 1;
    const int c  = tid & 63;
    const int tt = c >> 4;
    const float* Wp = gw1 + (size_t)tt * U_ * 16 + (c & 15);

    float acc[8];
#pragma unroll
    for (int r = 0; r < 8; r++) acc[r] = 0.f;

    for (int kc = 0; kc < U_ / 128; kc++) {
        __syncthreads();
#pragma unroll
        for (int p = 0; p < 8; p++) {
            const int idx = tid + p * 256;
            const int tz = idx >> 9, row = (idx >> 5) & 15, c4 = idx & 31;
            *(float4*)&s1[tz][row][c4 * 4] =
                *(const float4*)(g_task0 + ((size_t)tz * B_ + b0 + row) * U_ + kc * 128 + c4 * 4);
        }
        __syncthreads();
        if (active) {
            const float* wp = Wp + (size_t)kc * 128 * 16;
#pragma unroll 4
            for (int k = 0; k < 128; k += 4) {
                const float w0 = wp[(k + 0) * 16];
                const float w1 = wp[(k + 1) * 16];
                const float w2 = wp[(k + 2) * 16];
                const float w3 = wp[(k + 3) * 16];
#pragma unroll
                for (int r = 0; r < 8; r++) {
                    float4 xv = *(const float4*)&s1[tt][rh * 8 + r][k];
                    acc[r] += xv.x * w0 + xv.y * w1 + xv.z * w2 + xv.w * w3;
                }
            }
        }
    }
    if (active) {
        const float bb = gb1[c];
#pragma unroll
        for (int r = 0; r < 8; r++) sz[rh * 8 + r][c] = acc[r] + bb;
    }
    __syncthreads();

    if (tid < 64) {
        const int r = tid & 15, g = tid >> 4;
        float mx = -1e30f;
        for (int i = 0; i < 16; i++) mx = fmaxf(mx, sz[r][g * 16 + i]);
        float s = 0.f;
        for (int i = 0; i < 16; i++) s += expf(sz[r][g * 16 + i] - mx);
        const float inv = 1.f / s;
        float* o = g_g1 + ((size_t)g * B_ + b0 + r) * 16;
        for (int i = 0; i < 16; i++) o[i] = expf(sz[r][g * 16 + i] - mx) * inv;
    }
}

// ---------------------------------------------------------------------------
// Launch
// ---------------------------------------------------------------------------
extern "C" void kernel_launch(void* const* d_in, const int* in_sizes, int n_in,
                              void* d_out, int out_size) {
    (void)in_sizes; (void)n_in; (void)out_size;
    const float* x    = (const float*)d_in[0];
    const float* ews0 = (const float*)d_in[1];
    const float* ebs0 = (const float*)d_in[2];
    const float* ews1 = (const float*)d_in[3];
    const float* ebs1 = (const float*)d_in[4];
    const float* gws  = (const float*)d_in[5];
    const float* gbs  = (const float*)d_in[6];
    const float* ew0  = (const float*)d_in[7];
    const float* eb0  = (const float*)d_in[8];
    const float* gw0  = (const float*)d_in[9];
    const float* gb0  = (const float*)d_in[10];
    const float* ew1  = (const float*)d_in[11];
    const float* eb1  = (const float*)d_in[12];
    const float* gw1  = (const float*)d_in[13];
    const float* gb1  = (const float*)d_in[14];

    cudaFuncSetAttribute(fgemmS<D_>, cudaFuncAttributeMaxDynamicSharedMemorySize, SMEM_S);
    cudaFuncSetAttribute(fgemmS<U_>, cudaFuncAttributeMaxDynamicSharedMemorySize, SMEM_S);
    cudaFuncSetAttribute(fgemmB0, cudaFuncAttributeMaxDynamicSharedMemorySize, SMEM_B0);
    cudaFuncSetAttribute(fgemmB1, cudaFuncAttributeMaxDynamicSharedMemorySize, SMEM_B1);

    __half *xh, *bt0h, *bt1h, *a1h;
    cudaGetSymbolAddress((void**)&xh,   g_xh);
    cudaGetSymbolAddress((void**)&bt0h, g_bt0h);
    cudaGetSymbolAddress((void**)&bt1h, g_bt1h);
    cudaGetSymbolAddress((void**)&a1h,  g_a1h);

    // conversions
    convX<<<(B_ * D_ / 4) / 256, 256>>>(x, xh);
    ConvBArgs cb0;
    for (int t = 0; t < 4; t++) cb0.src[t] = ew0 + (size_t)t * D_ * UE;
    cb0.src[4] = ews0; cb0.hi = bt0h; cb0.K = D_;
    convB<<<dim3(NTOT / 32, D_ / 32, 5), dim3(32, 8)>>>(cb0);
    ConvBArgs cb1;
    for (int t = 0; t < 4; t++) cb1.src[t] = ew1 + (size_t)t * U_ * UE;
    cb1.src[4] = ews1; cb1.hi = bt1h; cb1.K = U_;
    convB<<<dim3(NTOT / 32, U_ / 32, 5), dim3(32, 8)>>>(cb1);

    // level 0
    gates0<<<B_ / 16, 256>>>(x, gw0, gb0, gws, gbs);
    fgemmS<D_><<<2048, 256, SMEM_S>>>(xh, bt0h + (size_t)4 * NTOT * D_, ebs0);
    FGArgs a0;
    for (int t = 0; t < 4; t++) {
        a0.Bh[t] = bt0h + (size_t)t * NTOT * D_;
        a0.bias[t] = eb0 + (size_t)t * UE;
    }
    fgemmB0<<<2048, 256, SMEM_B0>>>(a0);

    // level 1
    gates1<<<B_ / 16, 256>>>(gw1, gb1);
    fgemmS<U_><<<2048, 256, SMEM_S>>>(
        a1h + (size_t)4 * B_ * U_, bt1h + (size_t)4 * NTOT * U_, ebs1);
    FGArgs a1;
    for (int t = 0; t < 4; t++) {
        a1.Bh[t] = bt1h + (size_t)t * NTOT * U_;
        a1.bias[t] = eb1 + (size_t)t * UE;
    }
    fgemmB1<<<2048, 256, SMEM_B1>>>(a1, (float*)d_out);
}

// round 15
// speedup vs baseline: 5.5975x; 1.0130x over previous
#include <cuda_runtime.h>
#include <cuda_fp16.h>
#include <cstdint>

#define T_  4
#define B_  8192
#define D_  1024
#define U_  512
#define UE  4096
#define NTOT 4096

// ---------------------------------------------------------------------------
// Device scratch
// ---------------------------------------------------------------------------
__device__ __half g_xh[(size_t)B_ * D_];           // x in fp16
__device__ __half g_bt0h[5ull * NTOT * D_];        // level-0 B^T (N-major, fp16)
__device__ __half g_bt1h[5ull * NTOT * U_];
__device__ __half g_a1h[5ull * B_ * U_];           // level-1 A (4 tasks + share), fp16
__device__ float g_g0[(size_t)T_ * B_ * 16];
__device__ float g_gs[(size_t)B_ * 40];
__device__ float g_task0[(size_t)T_ * B_ * U_];    // fp32 (gates1 input)
__device__ float g_g1[(size_t)T_ * B_ * 16];

// ---------------------------------------------------------------------------
// PTX helpers (baseline sm_80+ only)
// ---------------------------------------------------------------------------
__device__ __forceinline__ uint32_t smem_u32(const void* p) {
    uint32_t a;
    asm("{ .reg .u64 t; cvta.to.shared.u64 t, %1; cvt.u32.u64 %0, t; }" : "=r"(a) : "l"(p));
    return a;
}
__device__ __forceinline__ void cp16(uint32_t dst, const void* src) {
    asm volatile("cp.async.cg.shared.global [%0], [%1], 16;" :: "r"(dst), "l"(src));
}
__device__ __forceinline__ void ldsm4(uint32_t* r, uint32_t addr) {
    asm volatile("ldmatrix.sync.aligned.m8n8.x4.shared.b16 {%0,%1,%2,%3}, [%4];"
        : "=r"(r[0]), "=r"(r[1]), "=r"(r[2]), "=r"(r[3]) : "r"(addr));
}
__device__ __forceinline__ void mma16816(float* c, const uint32_t* a, uint32_t b0, uint32_t b1) {
    asm volatile("mma.sync.aligned.m16n8k16.row.col.f32.f16.f16.f32 "
        "{%0,%1,%2,%3}, {%4,%5,%6,%7}, {%8,%9}, {%0,%1,%2,%3};"
        : "+f"(c[0]), "+f"(c[1]), "+f"(c[2]), "+f"(c[3])
        : "r"(a[0]), "r"(a[1]), "r"(a[2]), "r"(a[3]), "r"(b0), "r"(b1));
}
__device__ __forceinline__ float red4(float p) {
    p += __shfl_xor_sync(0xffffffffu, p, 1);
    p += __shfl_xor_sync(0xffffffffu, p, 2);
    return p;
}
__device__ __forceinline__ void store_h4(__half* h, size_t off, float4 v) {
    *(__half2*)&h[off]     = __half2(__float2half_rn(v.x), __float2half_rn(v.y));
    *(__half2*)&h[off + 2] = __half2(__float2half_rn(v.z), __float2half_rn(v.w));
}

// ---------------------------------------------------------------------------
// Conversions (fp32 -> fp16; B transposed to N-major)
// ---------------------------------------------------------------------------
__global__ void convX(const float* __restrict__ x, __half* __restrict__ hi) {
    size_t i = (size_t)blockIdx.x * blockDim.x + threadIdx.x;
    float4 v = ((const float4*)x)[i];
    store_h4(hi, 4 * i, v);
}

struct ConvBArgs { const float* src[5]; __half* hi; int K; };

__global__ void convB(ConvBArgs a) {
    __shared__ float s[32][33];
    const int z = blockIdx.z;
    const float* __restrict__ src = a.src[z];
    const int n0 = blockIdx.x * 32, k0 = blockIdx.y * 32;
    const int tx = threadIdx.x, ty = threadIdx.y;
#pragma unroll
    for (int i = 0; i < 4; i++)
        s[ty + i * 8][tx] = src[(size_t)(k0 + ty + i * 8) * UE + n0 + tx];
    __syncthreads();
    __half* oh = a.hi + (size_t)z * NTOT * a.K;
#pragma unroll
    for (int i = 0; i < 4; i++) {
        const int n = n0 + ty + i * 8, k = k0 + tx;
        oh[(size_t)n * a.K + k] = __float2half_rn(s[tx][ty + i * 8]);
    }
}

// ---------------------------------------------------------------------------
// GEMM machinery: 128x128 tile, K-step 32, 3-stage cp.async, 8 warps,
// single-product fp16 (Ah x Bh).
// ---------------------------------------------------------------------------
#define MAT_BYTES 8192
#define STAGE_BYTES (2 * MAT_BYTES)         // 16 KB: Ah, Bh
#define SM_STK  (3 * STAGE_BYTES)           // staging float[128][16]  @48KB
#define SM_SSH  (SM_STK + 8192)             // share accum float[128][16]
#define SM_SES  (SM_SSH + 8192)             // es tile __half[128][128] (32 KB)
#define SMEM_B  (SM_SES + 32768)            // 96 KB total

template<int KK>
__device__ __forceinline__ void kloop(const __half* __restrict__ A_h,
                                      const __half* __restrict__ B_h,
                                      uint32_t sb, int rlo, int ch, int dsw,
                                      const uint32_t (&aoff)[2][2],
                                      const uint32_t (&boff)[4][2],
                                      float (&acc)[2][8][4]) {
    constexpr int nk = KK / 32;
    const __half* srcs[2] = { A_h, B_h };
    auto load_stage = [&](int buf, int kc) {
        const uint32_t base = sb + (uint32_t)buf * STAGE_BYTES;
#pragma unroll
        for (int i = 0; i < 4; i++) {
            const int mat = i >> 1;
            const int r   = ((i & 1) << 6) + rlo;
            cp16(base + mat * MAT_BYTES + r * 64 + dsw,
                 srcs[mat] + (size_t)r * KK + kc + ch * 8);
        }
        asm volatile("cp.async.commit_group;" ::: "memory");
    };
    load_stage(0, 0);
    load_stage(1, 32);
    int cb = 0;
    for (int c = 0; c < nk; c++) {
        if (c + 1 < nk) asm volatile("cp.async.wait_group 1;" ::: "memory");
        else            asm volatile("cp.async.wait_group 0;" ::: "memory");
        __syncthreads();
        if (c + 2 < nk) {
            int nb = cb + 2; if (nb >= 3) nb -= 3;
            load_stage(nb, (c + 2) * 32);
        }
        const uint32_t st = sb + (uint32_t)cb * STAGE_BYTES;
        if (++cb == 3) cb = 0;
#pragma unroll
        for (int ks = 0; ks < 2; ks++) {
            uint32_t ah[2][4];
#pragma unroll
            for (int i = 0; i < 2; i++) ldsm4(ah[i], st + aoff[i][ks]);
            uint32_t bf[4][4];
#pragma unroll
            for (int j = 0; j < 4; j++) ldsm4(bf[j], st + MAT_BYTES + boff[j][ks]);
#pragma unroll
            for (int i = 0; i < 2; i++)
#pragma unroll
                for (int j = 0; j < 4; j++) {
                    mma16816(acc[i][2 * j],     ah[i], bf[j][0], bf[j][2]);
                    mma16816(acc[i][2 * j + 1], ah[i], bf[j][1], bf[j][3]);
                }
        }
    }
}

#define GEOM() \
    const int id = blockIdx.x; \
    const int nt = (id >> 4) & 31; \
    const int mt = (id & 15) + ((id >> 9) << 4); \
    const int n0 = nt << 7, m0 = mt << 7; \
    const int u0 = nt << 4; (void)u0; \
    const int tid = threadIdx.x; \
    const int lane = tid & 31; \
    const int w = tid >> 5, wm = w & 3, wn = w >> 2, hb = lane >> 4; \
    const int rlo = tid >> 2, ch = tid & 3; \
    const int dsw = ((ch ^ ((rlo >> 1) & 3)) << 4); \
    uint32_t aoff[2][2], boff[4][2]; \
    _Pragma("unroll") for (int i = 0; i < 2; i++) { \
        const int rA = 32 * wm + 16 * i + (lane & 15); \
        const int csw = (rA >> 1) & 3; \
        _Pragma("unroll") for (int ks = 0; ks < 2; ks++) \
            aoff[i][ks] = (uint32_t)(rA * 64 + (((2 * ks + hb) ^ csw) << 4)); \
    } \
    _Pragma("unroll") for (int j = 0; j < 4; j++) { \
        const int rB = 64 * wn + 16 * j + (((lane >> 3) & 1) << 3) + (lane & 7); \
        const int csw = (rB >> 1) & 3; \
        _Pragma("unroll") for (int ks = 0; ks < 2; ks++) \
            boff[j][ks] = (uint32_t)(rB * 64 + (((2 * ks + hb) ^ csw) << 4)); \
    }

#define ZERO_ACC() \
    float acc[2][8][4]; \
    _Pragma("unroll") for (int i = 0; i < 2; i++) \
        _Pragma("unroll") for (int j = 0; j < 8; j++) \
            _Pragma("unroll") for (int q = 0; q < 4; q++) acc[i][j][q] = 0.f;

struct FGArgs {
    const __half* Bh[5];     // 4 tasks + share
    const float* bias[5];
};

// ---------------------------------------------------------------------------
// Level-0 fused GEMM: share expert (t=4) -> smem es tile, then tasks t=0..3
// with gate combine; writes task0 fp32 + a1 fp16 (tasks and share).
// ---------------------------------------------------------------------------
__global__ __launch_bounds__(256, 2) void fgemmB0(FGArgs args) {
    extern __shared__ __align__(128) char smem[];
    const uint32_t sb = smem_u32(smem);
    float* stk = (float*)(smem + SM_STK);
    float* ssh = (float*)(smem + SM_SSH);
    __half* ses = (__half*)(smem + SM_SES);
    GEOM();
    for (int idx = tid; idx < 2048; idx += 256) ssh[idx] = 0.f;

    const __half* Ah = g_xh + (size_t)m0 * D_;
    const int e2 = 2 * (lane & 3);

    // ---- share expert -> es tile in smem (fp16) ----
    {
        ZERO_ACC();
        kloop<D_>(Ah, args.Bh[4] + (size_t)n0 * D_, sb, rlo, ch, dsw, aoff, boff, acc);
        const float* __restrict__ bias = args.bias[4];
#pragma unroll
        for (int i = 0; i < 2; i++) {
            const int r0 = 32 * wm + 16 * i + (lane >> 2), r1 = r0 + 8;
#pragma unroll
            for (int j = 0; j < 8; j++) {
                const int ncl = 64 * wn + 8 * j + e2;
                const float b0v = bias[n0 + ncl], b1v = bias[n0 + ncl + 1];
                *(__half2*)&ses[r0 * 128 + ncl] = __half2(
                    __float2half_rn(fmaxf(acc[i][j][0] + b0v, 0.f)),
                    __float2half_rn(fmaxf(acc[i][j][1] + b1v, 0.f)));
                *(__half2*)&ses[r1 * 128 + ncl] = __half2(
                    __float2half_rn(fmaxf(acc[i][j][2] + b0v, 0.f)),
                    __float2half_rn(fmaxf(acc[i][j][3] + b1v, 0.f)));
            }
        }
        __syncthreads();
    }

    // ---- tasks ----
#pragma unroll 1
    for (int t = 0; t < 4; t++) {
        ZERO_ACC();
        kloop<D_>(Ah, args.Bh[t] + (size_t)n0 * D_, sb, rlo, ch, dsw, aoff, boff, acc);

        const float* __restrict__ bias = args.bias[t];
#pragma unroll
        for (int i = 0; i < 2; i++) {
            const int r0 = 32 * wm + 16 * i + (lane >> 2), r1 = r0 + 8;
            const float2 ga0 = *(const float2*)&g_g0[((size_t)t * B_ + m0 + r0) * 16 + e2];
            const float2 gb0 = *(const float2*)&g_g0[((size_t)t * B_ + m0 + r0) * 16 + 8 + e2];
            const float2 ga1 = *(const float2*)&g_g0[((size_t)t * B_ + m0 + r1) * 16 + e2];
            const float2 gb1 = *(const float2*)&g_g0[((size_t)t * B_ + m0 + r1) * 16 + 8 + e2];
            const float2 gt0 = *(const float2*)&g_gs[(size_t)(m0 + r0) * 40 + t * 8 + e2];
            const float2 gt1 = *(const float2*)&g_gs[(size_t)(m0 + r1) * 40 + t * 8 + e2];
            float2 gq0 = {0.f, 0.f}, gq1 = {0.f, 0.f};
            if (t == 3) {
                gq0 = *(const float2*)&g_gs[(size_t)(m0 + r0) * 40 + 32 + e2];
                gq1 = *(const float2*)&g_gs[(size_t)(m0 + r1) * 40 + 32 + e2];
            }
#pragma unroll
            for (int j = 0; j < 8; j++) {
                const int ncl = 64 * wn + 8 * j + e2;
                const float b0v = bias[n0 + ncl], b1v = bias[n0 + ncl + 1];
                const float v00 = fmaxf(acc[i][j][0] + b0v, 0.f);
                const float v01 = fmaxf(acc[i][j][1] + b1v, 0.f);
                const float v10 = fmaxf(acc[i][j][2] + b0v, 0.f);
                const float v11 = fmaxf(acc[i][j][3] + b1v, 0.f);
                const float2 es0 = __half22float2(*(const __half2*)&ses[r0 * 128 + ncl]);
                const float2 es1 = __half22float2(*(const __half2*)&ses[r1 * 128 + ncl]);
                float pt0 = red4(v00 * ga0.x + v01 * ga0.y + es0.x * gb0.x + es0.y * gb0.y);
                float pt1 = red4(v10 * ga1.x + v11 * ga1.y + es1.x * gb1.x + es1.y * gb1.y);
                float ps0 = v00 * gt0.x + v01 * gt0.y;
                float ps1 = v10 * gt1.x + v11 * gt1.y;
                if (t == 3) {
                    ps0 += es0.x * gq0.x + es0.y * gq0.y;
                    ps1 += es1.x * gq1.x + es1.y * gq1.y;
                }
                ps0 = red4(ps0); ps1 = red4(ps1);
                if ((lane & 3) == 0) {
                    const int u = 8 * wn + j;
                    stk[r0 * 16 + u] = pt0;
                    stk[r1 * 16 + u] = pt1;
                    ssh[r0 * 16 + u] += ps0;
                    ssh[r1 * 16 + u] += ps1;
                }
            }
        }
        __syncthreads();
        for (int idx = tid; idx < 512; idx += 256) {
            const int r = idx >> 2, c4 = idx & 3;
            float4 tv = *(float4*)&stk[r * 16 + 4 * c4];
            const size_t off = ((size_t)t * B_ + m0 + r) * U_ + u0 + 4 * c4;
            *(float4*)&g_task0[off] = tv;
            store_h4(g_a1h, off, tv);
        }
        __syncthreads();
    }

    for (int idx = tid; idx < 512; idx += 256) {
        const int r = idx >> 2, c4 = idx & 3;
        float4 sv = *(float4*)&ssh[r * 16 + 4 * c4];
        store_h4(g_a1h, ((size_t)4 * B_ + m0 + r) * U_ + u0 + 4 * c4, sv);
    }
}

// ---------------------------------------------------------------------------
// Level-1 fused GEMM: share (t=4) -> es tile, then tasks; writes final out.
// ---------------------------------------------------------------------------
__global__ __launch_bounds__(256, 2) void fgemmB1(FGArgs args, float* __restrict__ out) {
    extern __shared__ __align__(128) char smem[];
    const uint32_t sb = smem_u32(smem);
    float* stk = (float*)(smem + SM_STK);
    __half* ses = (__half*)(smem + SM_SES);
    GEOM();
    const int e2 = 2 * (lane & 3);

    // ---- share expert -> es tile ----
    {
        ZERO_ACC();
        kloop<U_>(g_a1h + ((size_t)4 * B_ + m0) * U_, args.Bh[4] + (size_t)n0 * U_,
                  sb, rlo, ch, dsw, aoff, boff, acc);
        const float* __restrict__ bias = args.bias[4];
#pragma unroll
        for (int i = 0; i < 2; i++) {
            const int r0 = 32 * wm + 16 * i + (lane >> 2), r1 = r0 + 8;
#pragma unroll
            for (int j = 0; j < 8; j++) {
                const int ncl = 64 * wn + 8 * j + e2;
                const float b0v = bias[n0 + ncl], b1v = bias[n0 + ncl + 1];
                *(__half2*)&ses[r0 * 128 + ncl] = __half2(
                    __float2half_rn(fmaxf(acc[i][j][0] + b0v, 0.f)),
                    __float2half_rn(fmaxf(acc[i][j][1] + b1v, 0.f)));
                *(__half2*)&ses[r1 * 128 + ncl] = __half2(
                    __float2half_rn(fmaxf(acc[i][j][2] + b0v, 0.f)),
                    __float2half_rn(fmaxf(acc[i][j][3] + b1v, 0.f)));
            }
        }
        __syncthreads();
    }

#pragma unroll 1
    for (int t = 0; t < 4; t++) {
        ZERO_ACC();
        kloop<U_>(g_a1h + ((size_t)t * B_ + m0) * U_, args.Bh[t] + (size_t)n0 * U_,
                  sb, rlo, ch, dsw, aoff, boff, acc);

        const float* __restrict__ bias = args.bias[t];
#pragma unroll
        for (int i = 0; i < 2; i++) {
            const int r0 = 32 * wm + 16 * i + (lane >> 2), r1 = r0 + 8;
            const float2 ga0 = *(const float2*)&g_g1[((size_t)t * B_ + m0 + r0) * 16 + e2];
            const float2 gb0 = *(const float2*)&g_g1[((size_t)t * B_ + m0 + r0) * 16 + 8 + e2];
            const float2 ga1 = *(const float2*)&g_g1[((size_t)t * B_ + m0 + r1) * 16 + e2];
            const float2 gb1 = *(const float2*)&g_g1[((size_t)t * B_ + m0 + r1) * 16 + 8 + e2];
#pragma unroll
            for (int j = 0; j < 8; j++) {
                const int ncl = 64 * wn + 8 * j + e2;
                const float b0v = bias[n0 + ncl], b1v = bias[n0 + ncl + 1];
                const float v00 = fmaxf(acc[i][j][0] + b0v, 0.f);
                const float v01 = fmaxf(acc[i][j][1] + b1v, 0.f);
                const float v10 = fmaxf(acc[i][j][2] + b0v, 0.f);
                const float v11 = fmaxf(acc[i][j][3] + b1v, 0.f);
                const float2 es0 = __half22float2(*(const __half2*)&ses[r0 * 128 + ncl]);
                const float2 es1 = __half22float2(*(const __half2*)&ses[r1 * 128 + ncl]);
                float pt0 = red4(v00 * ga0.x + v01 * ga0.y + es0.x * gb0.x + es0.y * gb0.y);
                float pt1 = red4(v10 * ga1.x + v11 * ga1.y + es1.x * gb1.x + es1.y * gb1.y);
                if ((lane & 3) == 0) {
                    const int u = 8 * wn + j;
                    stk[r0 * 16 + u] = pt0;
                    stk[r1 * 16 + u] = pt1;
                }
            }
        }
        __syncthreads();
        for (int idx = tid; idx < 512; idx += 256) {
            const int r = idx >> 2, c4 = idx & 3;
            float4 tv = *(float4*)&stk[r * 16 + 4 * c4];
            *(float4*)&out[((size_t)t * B_ + m0 + r) * U_ + u0 + 4 * c4] = tv;
        }
        __syncthreads();
    }
}

// ---------------------------------------------------------------------------
// gates0 / gates1 (R8 fast versions, unchanged)
// ---------------------------------------------------------------------------
__global__ __launch_bounds__(256) void gates0(const float* __restrict__ x,
                                              const float* __restrict__ gw0,
                                              const float* __restrict__ gb0,
                                              const float* __restrict__ gws,
                                              const float* __restrict__ gbs) {
    const int b0 = blockIdx.x * 16;
    const int tid = threadIdx.x;
    __shared__ float sx[16][128];
    __shared__ float sz[16][104];

    const bool active = tid < 208;
    const int rh = (tid >= 104) ? 1 : 0;
    const int c  = active ? (tid - rh * 104) : 0;

    const float* Wp; int wstride;
    if (c < 64) { Wp = gw0 + (size_t)(c >> 4) * D_ * 16 + (c & 15); wstride = 16; }
    else        { Wp = gws + (c - 64);                              wstride = 40; }

    float acc[8];
#pragma unroll
    for (int r = 0; r < 8; r++) acc[r] = 0.f;

    for (int kc = 0; kc < D_ / 128; kc++) {
        __syncthreads();
#pragma unroll
        for (int p = 0; p < 2; p++) {
            const int idx = tid + p * 256;
            const int row = idx >> 5, c4 = idx & 31;
            *(float4*)&sx[row][c4 * 4] =
                *(const float4*)(x + (size_t)(b0 + row) * D_ + kc * 128 + c4 * 4);
        }
        __syncthreads();
        if (active) {
            const float* wp = Wp + (size_t)kc * 128 * wstride;
#pragma unroll 4
            for (int k = 0; k < 128; k += 4) {
                const float w0 = wp[(k + 0) * wstride];
                const float w1 = wp[(k + 1) * wstride];
                const float w2 = wp[(k + 2) * wstride];
                const float w3 = wp[(k + 3) * wstride];
#pragma unroll
                for (int r = 0; r < 8; r++) {
                    float4 xv = *(const float4*)&sx[rh * 8 + r][k];
                    acc[r] += xv.x * w0 + xv.y * w1 + xv.z * w2 + xv.w * w3;
                }
            }
        }
    }
    if (active) {
        const float bb = (c < 64) ? gb0[c] : gbs[c - 64];
#pragma unroll
        for (int r = 0; r < 8; r++) sz[rh * 8 + r][c] = acc[r] + bb;
    }
    __syncthreads();

    if (tid < 80) {
        const int r = tid & 15, g = tid >> 4;
        const int base = (g < 4) ? g * 16 : 64;
        const int len  = (g < 4) ? 16 : 40;
        float mx = -1e30f;
        for (int i = 0; i < len; i++) mx = fmaxf(mx, sz[r][base + i]);
        float s = 0.f;
        for (int i = 0; i < len; i++) s += expf(sz[r][base + i] - mx);
        const float inv = 1.f / s;
        if (g < 4) {
            float* o = g_g0 + ((size_t)g * B_ + b0 + r) * 16;
            for (int i = 0; i < 16; i++) o[i] = expf(sz[r][base + i] - mx) * inv;
        } else {
            float* o = g_gs + (size_t)(b0 + r) * 40;
            for (int i = 0; i < 40; i++) o[i] = expf(sz[r][base + i] - mx) * inv;
        }
    }
}

__global__ __launch_bounds__(256) void gates1(const float* __restrict__ gw1,
                                              const float* __restrict__ gb1) {
    const int b0 = blockIdx.x * 16;
    const int tid = threadIdx.x;
    __shared__ float s1[4][16][128];
    __shared__ float sz[16][64];

    const bool active = tid < 128;
    const int rh = (tid >> 6) & 1;
    const int c  = tid & 63;
    const int tt = c >> 4;
    const float* Wp = gw1 + (size_t)tt * U_ * 16 + (c & 15);

    float acc[8];
#pragma unroll
    for (int r = 0; r < 8; r++) acc[r] = 0.f;

    for (int kc = 0; kc < U_ / 128; kc++) {
        __syncthreads();
#pragma unroll
        for (int p = 0; p < 8; p++) {
            const int idx = tid + p * 256;
            const int tz = idx >> 9, row = (idx >> 5) & 15, c4 = idx & 31;
            *(float4*)&s1[tz][row][c4 * 4] =
                *(const float4*)(g_task0 + ((size_t)tz * B_ + b0 + row) * U_ + kc * 128 + c4 * 4);
        }
        __syncthreads();
        if (active) {
            const float* wp = Wp + (size_t)kc * 128 * 16;
#pragma unroll 4
            for (int k = 0; k < 128; k += 4) {
                const float w0 = wp[(k + 0) * 16];
                const float w1 = wp[(k + 1) * 16];
                const float w2 = wp[(k + 2) * 16];
                const float w3 = wp[(k + 3) * 16];
#pragma unroll
                for (int r = 0; r < 8; r++) {
                    float4 xv = *(const float4*)&s1[tt][rh * 8 + r][k];
                    acc[r] += xv.x * w0 + xv.y * w1 + xv.z * w2 + xv.w * w3;
                }
            }
        }
    }
    if (active) {
        const float bb = gb1[c];
#pragma unroll
        for (int r = 0; r < 8; r++) sz[rh * 8 + r][c] = acc[r] + bb;
    }
    __syncthreads();

    if (tid < 64) {
        const int r = tid & 15, g = tid >> 4;
        float mx = -1e30f;
        for (int i = 0; i < 16; i++) mx = fmaxf(mx, sz[r][g * 16 + i]);
        float s = 0.f;
        for (int i = 0; i < 16; i++) s += expf(sz[r][g * 16 + i] - mx);
        const float inv = 1.f / s;
        float* o = g_g1 + ((size_t)g * B_ + b0 + r) * 16;
        for (int i = 0; i < 16; i++) o[i] = expf(sz[r][g * 16 + i] - mx) * inv;
    }
}

// ---------------------------------------------------------------------------
// Launch
// ---------------------------------------------------------------------------
extern "C" void kernel_launch(void* const* d_in, const int* in_sizes, int n_in,
                              void* d_out, int out_size) {
    (void)in_sizes; (void)n_in; (void)out_size;
    const float* x    = (const float*)d_in[0];
    const float* ews0 = (const float*)d_in[1];
    const float* ebs0 = (const float*)d_in[2];
    const float* ews1 = (const float*)d_in[3];
    const float* ebs1 = (const float*)d_in[4];
    const float* gws  = (const float*)d_in[5];
    const float* gbs  = (const float*)d_in[6];
    const float* ew0  = (const float*)d_in[7];
    const float* eb0  = (const float*)d_in[8];
    const float* gw0  = (const float*)d_in[9];
    const float* gb0  = (const float*)d_in[10];
    const float* ew1  = (const float*)d_in[11];
    const float* eb1  = (const float*)d_in[12];
    const float* gw1  = (const float*)d_in[13];
    const float* gb1  = (const float*)d_in[14];

    cudaFuncSetAttribute(fgemmB0, cudaFuncAttributeMaxDynamicSharedMemorySize, SMEM_B);
    cudaFuncSetAttribute(fgemmB1, cudaFuncAttributeMaxDynamicSharedMemorySize, SMEM_B);

    __half *xh, *bt0h, *bt1h, *a1h;
    cudaGetSymbolAddress((void**)&xh,   g_xh);
    cudaGetSymbolAddress((void**)&bt0h, g_bt0h);
    cudaGetSymbolAddress((void**)&bt1h, g_bt1h);
    cudaGetSymbolAddress((void**)&a1h,  g_a1h);

    // conversions
    convX<<<(B_ * D_ / 4) / 256, 256>>>(x, xh);
    ConvBArgs cb0;
    for (int t = 0; t < 4; t++) cb0.src[t] = ew0 + (size_t)t * D_ * UE;
    cb0.src[4] = ews0; cb0.hi = bt0h; cb0.K = D_;
    convB<<<dim3(NTOT / 32, D_ / 32, 5), dim3(32, 8)>>>(cb0);
    ConvBArgs cb1;
    for (int t = 0; t < 4; t++) cb1.src[t] = ew1 + (size_t)t * U_ * UE;
    cb1.src[4] = ews1; cb1.hi = bt1h; cb1.K = U_;
    convB<<<dim3(NTOT / 32, U_ / 32, 5), dim3(32, 8)>>>(cb1);

    // level 0
    gates0<<<B_ / 16, 256>>>(x, gw0, gb0, gws, gbs);
    FGArgs a0;
    for (int t = 0; t < 4; t++) {
        a0.Bh[t] = bt0h + (size_t)t * NTOT * D_;
        a0.bias[t] = eb0 + (size_t)t * UE;
    }
    a0.Bh[4] = bt0h + (size_t)4 * NTOT * D_;
    a0.bias[4] = ebs0;
    fgemmB0<<<2048, 256, SMEM_B>>>(a0);

    // level 1
    gates1<<<B_ / 16, 256>>>(gw1, gb1);
    FGArgs a1;
    for (int t = 0; t < 4; t++) {
        a1.Bh[t] = bt1h + (size_t)t * NTOT * U_;
        a1.bias[t] = eb1 + (size_t)t * UE;
    }
    a1.Bh[4] = bt1h + (size_t)4 * NTOT * U_;
    a1.bias[4] = ebs1;
    fgemmB1<<<2048, 256, SMEM_B>>>(a1, (float*)d_out);
}